// round 10
// baseline (speedup 1.0000x reference)
#include <cuda_runtime.h>
#include <cuda_bf16.h>
#include <math.h>
#include <stdint.h>

#define BB   32
#define LL   4096
#define CC   512
#define WSZ  64
#define SHIFT 32
#define NH   8
#define DK   64
#define HID  2048
#define NW   64
#define TOK  (BB*LL)
#define Y_ELEMS   ((size_t)TOK*CC)
#define ATTN_ELEMS ((size_t)BB*NW*NH*WSZ*WSZ)
#define PLANE 8192              // elements per 128x64 bf16 plane (16KB)

// ---------------- scratch ----------------------------------------------------
// packed layout: group g, k-plane ki, split s(0=hi,1=lo):
//   offset = ((g*KT + ki)*2 + s) * PLANE       (hi/lo adjacent -> 32KB TMA)
__device__ __nv_bfloat16 g_hp   [(size_t)TOK*2*CC];
__device__ __nv_bfloat16 g_ctxp [(size_t)TOK*2*CC];
__device__ __nv_bfloat16 g_f2p  [(size_t)TOK*2*HID];
__device__ __nv_bfloat16 g_wqkvp[(size_t)(3*CC)*2*CC];
__device__ __nv_bfloat16 g_wop  [(size_t)CC*2*CC];
__device__ __nv_bfloat16 g_c1wp [(size_t)HID*2*CC];
__device__ __nv_bfloat16 g_c3wp [(size_t)CC*2*HID];
__device__ float g_q[(size_t)TOK*CC];   // q; reused as y1
__device__ float g_k[(size_t)TOK*CC];
__device__ float g_v[(size_t)TOK*CC];
__device__ float g_f[(size_t)TOK*HID];  // c1 out fp32

__device__ __forceinline__ float gelu_f(float x) {
    return 0.5f * x * (1.0f + erff(x * 0.70710678118654752440f));
}
__device__ __forceinline__ uint32_t pack_bf2(__nv_bfloat16 a, __nv_bfloat16 b) {
    return (uint32_t)__bfloat16_as_ushort(a) | ((uint32_t)__bfloat16_as_ushort(b) << 16);
}
__device__ __forceinline__ void store_hl8(
    __nv_bfloat16* hi, __nv_bfloat16* lo, int r, int cc, float4 v)
{
    int off = r * 128 + cc * 2;
    int sw  = off ^ ((off >> 3) & 0x70);
    __nv_bfloat16 h0 = __float2bfloat16(v.x), h1 = __float2bfloat16(v.y);
    __nv_bfloat16 h2 = __float2bfloat16(v.z), h3 = __float2bfloat16(v.w);
    __nv_bfloat16 l0 = __float2bfloat16(v.x - __bfloat162float(h0));
    __nv_bfloat16 l1 = __float2bfloat16(v.y - __bfloat162float(h1));
    __nv_bfloat16 l2 = __float2bfloat16(v.z - __bfloat162float(h2));
    __nv_bfloat16 l3 = __float2bfloat16(v.w - __bfloat162float(h3));
    *(uint2*)((char*)hi + sw) = make_uint2(pack_bf2(h0, h1), pack_bf2(h2, h3));
    *(uint2*)((char*)lo + sw) = make_uint2(pack_bf2(l0, l1), pack_bf2(l2, l3));
}
__device__ __forceinline__ __nv_bfloat16* planeptr(
    __nv_bfloat16* buf, int g, int s, int ki, int KT)
{
    return buf + (((size_t)g * KT + ki) * 2 + s) * PLANE;
}

// ---------------- weight prep -------------------------------------------------
__global__ void __launch_bounds__(256) prep_weights(
    const float* __restrict__ W, __nv_bfloat16* __restrict__ Wp,
    int K, int groupOffset)
{
    const int g = blockIdx.x, ki = blockIdx.y;
    const int KT = K >> 6;
    const int t = threadIdx.x;
    const int r = t >> 1, c0 = (t & 1) * 32;
    __nv_bfloat16* hi = planeptr(Wp, groupOffset + g, 0, ki, KT);
    __nv_bfloat16* lo = planeptr(Wp, groupOffset + g, 1, ki, KT);
    const float* src = W + (size_t)(g * 128 + r) * K + ki * 64;
    #pragma unroll
    for (int i = 0; i < 8; i++) {
        int c = c0 + i * 4;
        store_hl8(hi, lo, r, c, *(const float4*)(src + c));
    }
}

// ---------------- LayerNorm (+roll) -> packed planes (KT=8) -------------------
__global__ void __launch_bounds__(128) ln_kernel(
    const float* __restrict__ x, __nv_bfloat16* __restrict__ outp,
    const float* __restrict__ g, const float* __restrict__ b, int rolled)
{
    int row = blockIdx.x;
    int bt  = row >> 12, l = row & (LL - 1);
    int src = rolled ? ((bt << 12) | ((l + SHIFT) & (LL - 1))) : row;
    const float* xr = x + (size_t)src * CC;

    int t = threadIdx.x;
    float4 v = *(const float4*)(xr + t * 4);
    float s  = v.x + v.y + v.z + v.w;
    float ss = v.x*v.x + v.y*v.y + v.z*v.z + v.w*v.w;
    #pragma unroll
    for (int o = 16; o > 0; o >>= 1) {
        s  += __shfl_xor_sync(0xffffffffu, s,  o);
        ss += __shfl_xor_sync(0xffffffffu, ss, o);
    }
    __shared__ float red[8];
    int wid = t >> 5, lid = t & 31;
    if (lid == 0) { red[wid] = s; red[4 + wid] = ss; }
    __syncthreads();
    s  = red[0] + red[1] + red[2] + red[3];
    ss = red[4] + red[5] + red[6] + red[7];
    float mean = s * (1.0f / CC);
    float rstd = rsqrtf(ss * (1.0f / CC) - mean * mean + 1e-5f);

    float4 gg = *(const float4*)(g + t * 4);
    float4 bb = *(const float4*)(b + t * 4);
    float4 o4;
    o4.x = (v.x - mean) * rstd * gg.x + bb.x;
    o4.y = (v.y - mean) * rstd * gg.y + bb.y;
    o4.z = (v.z - mean) * rstd * gg.z + bb.z;
    o4.w = (v.w - mean) * rstd * gg.w + bb.w;

    int mi = row >> 7, r = row & 127;
    int ki = t >> 4, cc = (4 * t) & 63;
    store_hl8(planeptr(outp, mi, 0, ki, 8), planeptr(outp, mi, 1, ki, 8), r, cc, o4);
}

// ---------------- async-feed bf16x3 mma.sync GEMM -----------------------------
__device__ __forceinline__ uint32_t cvta_smem(const void* p) {
    return (uint32_t)__cvta_generic_to_shared(p);
}
__device__ __forceinline__ void ldsm4(uint32_t* r, uint32_t addr) {
    asm volatile("ldmatrix.sync.aligned.m8n8.x4.shared.b16 {%0,%1,%2,%3}, [%4];"
        : "=r"(r[0]), "=r"(r[1]), "=r"(r[2]), "=r"(r[3]) : "r"(addr));
}
__device__ __forceinline__ void mma16816(float* c, const uint32_t* a, const uint32_t* b) {
    asm volatile("mma.sync.aligned.m16n8k16.row.col.f32.bf16.bf16.f32 "
        "{%0,%1,%2,%3},{%4,%5,%6,%7},{%8,%9},{%0,%1,%2,%3};"
        : "+f"(c[0]), "+f"(c[1]), "+f"(c[2]), "+f"(c[3])
        : "r"(a[0]), "r"(a[1]), "r"(a[2]), "r"(a[3]), "r"(b[0]), "r"(b[1]));
}
__device__ __forceinline__ void mbar_init(uint32_t a, uint32_t c) {
    asm volatile("mbarrier.init.shared.b64 [%0], %1;" :: "r"(a), "r"(c) : "memory");
}
__device__ __forceinline__ void mbar_expect_tx(uint32_t a, uint32_t bytes) {
    asm volatile("mbarrier.arrive.expect_tx.shared.b64 _, [%0], %1;"
                 :: "r"(a), "r"(bytes) : "memory");
}
__device__ __forceinline__ void mbar_arrive(uint32_t a) {
    asm volatile("mbarrier.arrive.shared.b64 _, [%0];" :: "r"(a) : "memory");
}
__device__ __forceinline__ void mbar_wait(uint32_t a, uint32_t p) {
    asm volatile(
        "{\n\t.reg .pred P;\n\tLW%=:\n\t"
        "mbarrier.try_wait.parity.acquire.cta.shared::cta.b64 P, [%0], %1;\n\t"
        "@!P bra LW%=;\n\t}" :: "r"(a), "r"(p) : "memory");
}
__device__ __forceinline__ void bulk_cp(uint32_t dst, const void* src,
                                        uint32_t bytes, uint32_t mbar) {
    asm volatile(
        "cp.async.bulk.shared::cluster.global.mbarrier::complete_tx::bytes "
        "[%0], [%1], %2, [%3];"
        :: "r"(dst), "l"(src), "r"(bytes), "r"(mbar) : "memory");
}
__device__ __forceinline__ uint32_t segaddr(uint32_t base, int r, int kc) {
    return base + r * 128 + ((((kc >> 3) ^ (r & 7)) & 7) << 4);
}

#define SBYTES 98304u   // Ah|Al | B0h|B0l | B1h|B1l

// MODE 0: qkv split  1: roll+residual  2: +bias GELU  3: +bias+addsrc
template<int MODE>
__global__ void __launch_bounds__(288) tc_gemm(
    const __nv_bfloat16* __restrict__ Ap, const __nv_bfloat16* __restrict__ Bp,
    float* __restrict__ O0, float* __restrict__ O1, float* __restrict__ O2,
    const float* __restrict__ bias, const float* __restrict__ addsrc,
    int KT, int Ntot)
{
    extern __shared__ char dsm[];
    __shared__ __align__(8) uint64_t s_mbar[4];   // full0 full1 empty0 empty1

    const uint32_t sb  = (cvta_smem(dsm) + 1023u) & ~1023u;
    const uint32_t mbF = cvta_smem(&s_mbar[0]);
    const uint32_t mbE = cvta_smem(&s_mbar[2]);
    const int tid = threadIdx.x;
    const int wid = tid >> 5, lane = tid & 31;
    const int ni = blockIdx.x, mi = blockIdx.y;

    if (tid == 0) {
        mbar_init(mbF, 1); mbar_init(mbF + 8, 1);
        mbar_init(mbE, 8); mbar_init(mbE + 8, 8);
        asm volatile("fence.proxy.async.shared::cta;" ::: "memory");
    }
    __syncthreads();

    if (wid == 8) {
        // ---- producer warp ----
        if (lane == 0) {
            for (int s = 0; s < KT; s++) {
                if (s >= 2) mbar_wait(mbE + (s & 1) * 8, (uint32_t)(((s - 2) >> 1) & 1));
                int b = s & 1;
                uint32_t d = sb + b * SBYTES;
                uint32_t m = mbF + b * 8;
                mbar_expect_tx(m, SBYTES);
                bulk_cp(d,         Ap + (((size_t)mi       * KT + s) * 2) * PLANE, 32768, m);
                bulk_cp(d + 32768, Bp + (((size_t)(2*ni)   * KT + s) * 2) * PLANE, 32768, m);
                bulk_cp(d + 65536, Bp + (((size_t)(2*ni+1) * KT + s) * 2) * PLANE, 32768, m);
            }
        }
        return;
    }

    // ---- consumer warps (0-7) ----
    const int wm = (wid & 1) * 64;
    const int wn = (wid >> 1) * 64;

    float acc[4][8][4];
    #pragma unroll
    for (int a = 0; a < 4; a++)
        #pragma unroll
        for (int b = 0; b < 8; b++)
            #pragma unroll
            for (int c = 0; c < 4; c++) acc[a][b][c] = 0.0f;

    const int bplane = (wn >> 7);
    const int wnl = wn & 127;
    const int arow0 = wm + (lane & 15);
    const int akc0  = (lane >> 4) * 8;
    const int brow0 = wnl + ((lane >> 4) & 1) * 8 + (lane & 7);
    const int bkc0  = ((lane >> 3) & 1) * 8;

    for (int s = 0; s < KT; s++) {
        int b = s & 1;
        mbar_wait(mbF + b * 8, (uint32_t)((s >> 1) & 1));
        const uint32_t Ah = sb + b * SBYTES;
        const uint32_t Al = Ah + 16384;
        const uint32_t Bh = Ah + 32768 + bplane * 32768;
        const uint32_t Bl = Bh + 16384;

        #pragma unroll
        for (int kf = 0; kf < 4; kf++) {
            const int k0 = kf * 16;
            uint32_t fa[4][4], fal[4][4], fb[4][4];
            const int akc = k0 + akc0;
            const int bkc = k0 + bkc0;
            #pragma unroll
            for (int mt = 0; mt < 4; mt++)
                ldsm4(fa[mt], segaddr(Ah, arow0 + mt * 16, akc));
            #pragma unroll
            for (int j = 0; j < 4; j++)
                ldsm4(fb[j], segaddr(Bh, brow0 + j * 16, bkc));
            #pragma unroll
            for (int mt = 0; mt < 4; mt++)
                #pragma unroll
                for (int j = 0; j < 4; j++) {
                    mma16816(acc[mt][2*j],   fa[mt], &fb[j][0]);
                    mma16816(acc[mt][2*j+1], fa[mt], &fb[j][2]);
                }
            #pragma unroll
            for (int mt = 0; mt < 4; mt++)
                ldsm4(fal[mt], segaddr(Al, arow0 + mt * 16, akc));
            #pragma unroll
            for (int mt = 0; mt < 4; mt++)
                #pragma unroll
                for (int j = 0; j < 4; j++) {
                    mma16816(acc[mt][2*j],   fal[mt], &fb[j][0]);
                    mma16816(acc[mt][2*j+1], fal[mt], &fb[j][2]);
                }
            #pragma unroll
            for (int j = 0; j < 4; j++)
                ldsm4(fb[j], segaddr(Bl, brow0 + j * 16, bkc));
            // stage buffer fully read once the final ldsm batch completes:
            // release it early so the producer can overlap the next TMA with
            // the remaining MMA pass.
            if (kf == 3 && lane == 0) mbar_arrive(mbE + b * 8);
            #pragma unroll
            for (int mt = 0; mt < 4; mt++)
                #pragma unroll
                for (int j = 0; j < 4; j++) {
                    mma16816(acc[mt][2*j],   fa[mt], &fb[j][0]);
                    mma16816(acc[mt][2*j+1], fa[mt], &fb[j][2]);
                }
        }
    }

    // epilogue
    const int rb = mi * 128 + wm + (lane >> 2);
    const int cb = wn + (lane & 3) * 2;
    #pragma unroll
    for (int mt = 0; mt < 4; mt++) {
        #pragma unroll
        for (int half = 0; half < 2; half++) {
            const int m = rb + mt * 16 + half * 8;
            #pragma unroll
            for (int nt = 0; nt < 8; nt++) {
                const int n = ni * 256 + cb + nt * 8;
                float v0 = acc[mt][nt][half * 2 + 0];
                float v1 = acc[mt][nt][half * 2 + 1];
                if (MODE == 0) {
                    int buf = n >> 9, col = n & 511;
                    float* dst = (buf == 0 ? O0 : (buf == 1 ? O1 : O2));
                    *(float2*)(dst + (size_t)m * CC + col) = make_float2(v0, v1);
                } else if (MODE == 1) {
                    int bt = m >> 12, l = m & (LL - 1);
                    size_t mrow = ((size_t)(bt << 12) | ((l + SHIFT) & (LL - 1)));
                    float2 r0 = *(const float2*)(addsrc + mrow * Ntot + n);
                    *(float2*)(O0 + mrow * Ntot + n) = make_float2(v0 + r0.x, v1 + r0.y);
                } else if (MODE == 2) {
                    float2 b2 = *(const float2*)(bias + n);
                    *(float2*)(O0 + (size_t)m * Ntot + n) =
                        make_float2(gelu_f(v0 + b2.x), gelu_f(v1 + b2.y));
                } else {
                    float2 b2 = *(const float2*)(bias + n);
                    float2 r0 = *(const float2*)(addsrc + (size_t)m * Ntot + n);
                    *(float2*)(O0 + (size_t)m * Ntot + n) =
                        make_float2(v0 + b2.x + r0.x, v1 + b2.y + r0.y);
                }
            }
        }
    }
}

// ---------------- window attention: 4x4 microtile version ---------------------
// dyn smem: sQ[64][68] (QT then S), sK[64][64] (KT), sV[64][64], sB[128]
#define ATT_SQ   0
#define ATT_SK   (64*68)
#define ATT_SV   (ATT_SK + 64*64)
#define ATT_SB   (ATT_SV + 64*64)
#define ATT_SMEM ((ATT_SB + 128) * 4)

__global__ void __launch_bounds__(256) attn_kernel(
    const float* __restrict__ q, const float* __restrict__ k, const float* __restrict__ v,
    const float* __restrict__ rel_table,
    float* __restrict__ attn_out, __nv_bfloat16* __restrict__ ctxp, int write_attn)
{
    extern __shared__ float smf[];
    float* sQ = smf + ATT_SQ;    // [d][t] stride 68 ; later S[t2][t] stride 68
    float* sK = smf + ATT_SK;    // [d][t2] stride 64
    float* sV = smf + ATT_SV;    // [t2][d] stride 64
    float* sB = smf + ATT_SB;    // bias column for this head

    const int h = blockIdx.x;
    const int w = blockIdx.y;
    const int tid = threadIdx.x;
    const size_t base = (size_t)w * WSZ * CC + (size_t)h * DK;

    {   // load q/k transposed, v direct
        int t = tid >> 2, qd = tid & 3;
        #pragma unroll
        for (int i = 0; i < 4; i++) {
            int d0 = qd * 16 + i * 4;
            float4 qv = *(const float4*)(q + base + (size_t)t * CC + d0);
            sQ[(d0+0)*68 + t] = qv.x; sQ[(d0+1)*68 + t] = qv.y;
            sQ[(d0+2)*68 + t] = qv.z; sQ[(d0+3)*68 + t] = qv.w;
            float4 kv = *(const float4*)(k + base + (size_t)t * CC + d0);
            sK[(d0+0)*64 + t] = kv.x; sK[(d0+1)*64 + t] = kv.y;
            sK[(d0+2)*64 + t] = kv.z; sK[(d0+3)*64 + t] = kv.w;
            float4 vv = *(const float4*)(v + base + (size_t)t * CC + d0);
            *(float4*)(sV + t * 64 + d0) = vv;
        }
        if (tid < 127) sB[tid] = rel_table[tid * NH + h];
    }
    __syncthreads();

    const int ty = tid >> 4, tx = tid & 15;      // 16x16 thread grid
    float sc[4][4];
    #pragma unroll
    for (int i = 0; i < 4; i++)
        #pragma unroll
        for (int j = 0; j < 4; j++) sc[i][j] = 0.0f;

    #pragma unroll 8
    for (int d = 0; d < 64; d++) {
        float4 qv = *(const float4*)(sQ + d * 68 + ty * 4);
        float4 kv = *(const float4*)(sK + d * 64 + tx * 4);
        float qa[4] = {qv.x, qv.y, qv.z, qv.w};
        float ka[4] = {kv.x, kv.y, kv.z, kv.w};
        #pragma unroll
        for (int i = 0; i < 4; i++)
            #pragma unroll
            for (int j = 0; j < 4; j++)
                sc[i][j] += qa[i] * ka[j];
    }

    const bool last = ((w & (NW - 1)) == (NW - 1));
    #pragma unroll
    for (int i = 0; i < 4; i++) {
        int t = ty * 4 + i;
        #pragma unroll
        for (int j = 0; j < 4; j++) {
            int t2 = tx * 4 + j;
            float s = sc[i][j] * 0.125f + sB[t - t2 + 63];
            if (last && ((t < 32) != (t2 < 32))) s -= 100.0f;
            sc[i][j] = s;
        }
    }

    // softmax over t2 (16 tx threads x 4 j)
    #pragma unroll
    for (int i = 0; i < 4; i++) {
        float m = fmaxf(fmaxf(sc[i][0], sc[i][1]), fmaxf(sc[i][2], sc[i][3]));
        m = fmaxf(m, __shfl_xor_sync(0xffffffffu, m, 1));
        m = fmaxf(m, __shfl_xor_sync(0xffffffffu, m, 2));
        m = fmaxf(m, __shfl_xor_sync(0xffffffffu, m, 4));
        m = fmaxf(m, __shfl_xor_sync(0xffffffffu, m, 8));
        float s = 0.0f;
        #pragma unroll
        for (int j = 0; j < 4; j++) { sc[i][j] = __expf(sc[i][j] - m); s += sc[i][j]; }
        s += __shfl_xor_sync(0xffffffffu, s, 1);
        s += __shfl_xor_sync(0xffffffffu, s, 2);
        s += __shfl_xor_sync(0xffffffffu, s, 4);
        s += __shfl_xor_sync(0xffffffffu, s, 8);
        float inv = 1.0f / s;
        #pragma unroll
        for (int j = 0; j < 4; j++) sc[i][j] *= inv;
    }

    if (write_attn) {
        #pragma unroll
        for (int i = 0; i < 4; i++) {
            int t = ty * 4 + i;
            size_t ao = ((((size_t)w * NH + h) * WSZ) + t) * WSZ + tx * 4;
            *(float4*)(attn_out + ao) = make_float4(sc[i][0], sc[i][1], sc[i][2], sc[i][3]);
        }
    }

    __syncthreads();                 // everyone done reading sQ (QT)
    #pragma unroll
    for (int i = 0; i < 4; i++) {
        int t = ty * 4 + i;
        #pragma unroll
        for (int j = 0; j < 4; j++)
            sQ[(tx * 4 + j) * 68 + t] = sc[i][j];    // S[t2][t]
    }
    __syncthreads();

    float oa[4][4];
    #pragma unroll
    for (int i = 0; i < 4; i++)
        #pragma unroll
        for (int j = 0; j < 4; j++) oa[i][j] = 0.0f;

    #pragma unroll 8
    for (int t2 = 0; t2 < 64; t2++) {
        float4 sv = *(const float4*)(sQ + t2 * 68 + ty * 4);
        float4 vv = *(const float4*)(sV + t2 * 64 + tx * 4);
        float sa[4] = {sv.x, sv.y, sv.z, sv.w};
        float va[4] = {vv.x, vv.y, vv.z, vv.w};
        #pragma unroll
        for (int i = 0; i < 4; i++)
            #pragma unroll
            for (int j = 0; j < 4; j++)
                oa[i][j] += sa[i] * va[j];
    }

    // packed ctx store
    #pragma unroll
    for (int i = 0; i < 4; i++) {
        int gr = w * WSZ + ty * 4 + i;
        int mi = gr >> 7, r = gr & 127;
        store_hl8(planeptr(ctxp, mi, 0, h, 8), planeptr(ctxp, mi, 1, h, 8),
                  r, tx * 4, make_float4(oa[i][0], oa[i][1], oa[i][2], oa[i][3]));
    }
}

// ---------------- dwconv (k=3) + GELU -> packed planes (KT=32) ----------------
__global__ void __launch_bounds__(256) dwconv_kernel(
    const float* __restrict__ f, const float* __restrict__ c2w,
    const float* __restrict__ c2b, __nv_bfloat16* __restrict__ outp)
{
    size_t idx = (size_t)blockIdx.x * blockDim.x + threadIdx.x;
    if (idx >= (size_t)TOK * HID / 4) return;
    size_t e = idx * 4;
    int ch = (int)(e % HID);
    size_t row = e / HID;
    int l = (int)(row & (LL - 1));

    float4 fc = *(const float4*)(f + e);
    float4 fm = make_float4(0.f, 0.f, 0.f, 0.f);
    float4 fp = make_float4(0.f, 0.f, 0.f, 0.f);
    if (l > 0)      fm = *(const float4*)(f + e - HID);
    if (l < LL - 1) fp = *(const float4*)(f + e + HID);

    float rr[4];
    float fmv[4] = {fm.x, fm.y, fm.z, fm.w};
    float fcv[4] = {fc.x, fc.y, fc.z, fc.w};
    float fpv[4] = {fp.x, fp.y, fp.z, fp.w};
    #pragma unroll
    for (int j = 0; j < 4; j++) {
        int c = ch + j;
        float dw = fmv[j] * c2w[c*3+0] + fcv[j] * c2w[c*3+1] + fpv[j] * c2w[c*3+2] + c2b[c];
        rr[j] = gelu_f(dw + fcv[j]);
    }
    int mi = (int)(row >> 7), r = (int)(row & 127);
    int ki = ch >> 6, cc = ch & 63;
    store_hl8(planeptr(outp, mi, 0, ki, 32), planeptr(outp, mi, 1, ki, 32),
              r, cc, make_float4(rr[0], rr[1], rr[2], rr[3]));
}

// ---------------- launch ------------------------------------------------------
extern "C" void kernel_launch(void* const* d_in, const int* in_sizes, int n_in,
                              void* d_out, int out_size)
{
    const float* x      = (const float*)d_in[0];
    const float* ln1_g  = (const float*)d_in[1];
    const float* ln1_b  = (const float*)d_in[2];
    const float* w_q    = (const float*)d_in[3];
    const float* w_k    = (const float*)d_in[4];
    const float* w_v    = (const float*)d_in[5];
    const float* w_o    = (const float*)d_in[6];
    const float* rel    = (const float*)d_in[7];
    const float* ln2_g  = (const float*)d_in[8];
    const float* ln2_b  = (const float*)d_in[9];
    const float* c1_w   = (const float*)d_in[10];
    const float* c1_b   = (const float*)d_in[11];
    const float* c2_w   = (const float*)d_in[12];
    const float* c2_b   = (const float*)d_in[13];
    const float* c3_w   = (const float*)d_in[14];
    const float* c3_b   = (const float*)d_in[15];
    float* out = (float*)d_out;

    __nv_bfloat16 *hp, *ctxp, *f2p, *wqkvp, *wop, *c1wp, *c3wp;
    float *q, *k, *v, *f;
    cudaGetSymbolAddress((void**)&hp,    g_hp);
    cudaGetSymbolAddress((void**)&ctxp,  g_ctxp);
    cudaGetSymbolAddress((void**)&f2p,   g_f2p);
    cudaGetSymbolAddress((void**)&wqkvp, g_wqkvp);
    cudaGetSymbolAddress((void**)&wop,   g_wop);
    cudaGetSymbolAddress((void**)&c1wp,  g_c1wp);
    cudaGetSymbolAddress((void**)&c3wp,  g_c3wp);
    cudaGetSymbolAddress((void**)&q, g_q);
    cudaGetSymbolAddress((void**)&k, g_k);
    cudaGetSymbolAddress((void**)&v, g_v);
    cudaGetSymbolAddress((void**)&f, g_f);
    float* y1 = q;

    const int write_attn = ((size_t)out_size >= Y_ELEMS + ATTN_ELEMS) ? 1 : 0;
    float* attn_out = out + Y_ELEMS;

    const int dyn = 2 * SBYTES + 1024;
    cudaFuncSetAttribute(tc_gemm<0>, cudaFuncAttributeMaxDynamicSharedMemorySize, dyn);
    cudaFuncSetAttribute(tc_gemm<1>, cudaFuncAttributeMaxDynamicSharedMemorySize, dyn);
    cudaFuncSetAttribute(tc_gemm<2>, cudaFuncAttributeMaxDynamicSharedMemorySize, dyn);
    cudaFuncSetAttribute(tc_gemm<3>, cudaFuncAttributeMaxDynamicSharedMemorySize, dyn);
    cudaFuncSetAttribute(attn_kernel, cudaFuncAttributeMaxDynamicSharedMemorySize, ATT_SMEM);

    // Launch order arranged so ncu (-s 5 -c 1) captures the qkv tc_gemm (idx 5).
    prep_weights<<<dim3(4, 8),  256>>>(w_q, wqkvp, CC, 0);    // 0
    prep_weights<<<dim3(4, 8),  256>>>(w_k, wqkvp, CC, 4);    // 1
    prep_weights<<<dim3(4, 8),  256>>>(w_v, wqkvp, CC, 8);    // 2
    ln_kernel<<<TOK, 128>>>(x, hp, ln1_g, ln1_b, 1);          // 3
    prep_weights<<<dim3(4, 8),  256>>>(w_o, wop,   CC, 0);    // 4

    tc_gemm<0><<<dim3(6, TOK/128), 288, dyn>>>(hp, wqkvp, q, k, v,
                                               nullptr, nullptr, 8, 1536);  // 5

    attn_kernel<<<dim3(NH, BB*NW), 256, ATT_SMEM>>>(q, k, v, rel, attn_out, ctxp, write_attn);

    tc_gemm<1><<<dim3(2, TOK/128), 288, dyn>>>(ctxp, wop, y1, nullptr, nullptr,
                                               nullptr, x, 8, CC);

    ln_kernel<<<TOK, 128>>>(y1, hp, ln2_g, ln2_b, 0);

    prep_weights<<<dim3(16, 8), 256>>>(c1_w, c1wp, CC, 0);
    tc_gemm<2><<<dim3(8, TOK/128), 288, dyn>>>(hp, c1wp, f, nullptr, nullptr,
                                               c1_b, nullptr, 8, HID);

    size_t nthread = (size_t)TOK * HID / 4;
    dwconv_kernel<<<(unsigned)((nthread + 255) / 256), 256>>>(f, c2_w, c2_b, f2p);

    prep_weights<<<dim3(4, 32), 256>>>(c3_w, c3wp, HID, 0);
    tc_gemm<3><<<dim3(2, TOK/128), 288, dyn>>>(f2p, c3wp, out, nullptr, nullptr,
                                               c3_b, y1, 32, CC);
}

// round 11
// speedup vs baseline: 1.0026x; 1.0026x over previous
#include <cuda_runtime.h>
#include <cuda_bf16.h>
#include <math.h>
#include <stdint.h>

#define BB   32
#define LL   4096
#define CC   512
#define WSZ  64
#define SHIFT 32
#define NH   8
#define DK   64
#define HID  2048
#define NW   64
#define TOK  (BB*LL)
#define Y_ELEMS   ((size_t)TOK*CC)
#define ATTN_ELEMS ((size_t)BB*NW*NH*WSZ*WSZ)
#define PLANE 8192              // elements per 128x64 bf16 plane (16KB)

// ---------------- scratch ----------------------------------------------------
// packed layout: group g, k-plane ki, split s(0=hi,1=lo):
//   offset = ((g*KT + ki)*2 + s) * PLANE       (hi/lo adjacent -> 32KB TMA)
__device__ __nv_bfloat16 g_hp   [(size_t)TOK*2*CC];
__device__ __nv_bfloat16 g_ctxp [(size_t)TOK*2*CC];
__device__ __nv_bfloat16 g_f2p  [(size_t)TOK*2*HID];
__device__ __nv_bfloat16 g_wqkvp[(size_t)(3*CC)*2*CC];
__device__ __nv_bfloat16 g_wop  [(size_t)CC*2*CC];
__device__ __nv_bfloat16 g_c1wp [(size_t)HID*2*CC];
__device__ __nv_bfloat16 g_c3wp [(size_t)CC*2*HID];
__device__ float g_q[(size_t)TOK*CC];   // q; reused as y1
__device__ float g_k[(size_t)TOK*CC];
__device__ float g_v[(size_t)TOK*CC];
__device__ float g_f[(size_t)TOK*HID];  // c1 out fp32

__device__ __forceinline__ float gelu_f(float x) {
    return 0.5f * x * (1.0f + erff(x * 0.70710678118654752440f));
}
__device__ __forceinline__ uint32_t pack_bf2(__nv_bfloat16 a, __nv_bfloat16 b) {
    return (uint32_t)__bfloat16_as_ushort(a) | ((uint32_t)__bfloat16_as_ushort(b) << 16);
}
__device__ __forceinline__ void store_hl8(
    __nv_bfloat16* hi, __nv_bfloat16* lo, int r, int cc, float4 v)
{
    int off = r * 128 + cc * 2;
    int sw  = off ^ ((off >> 3) & 0x70);
    __nv_bfloat16 h0 = __float2bfloat16(v.x), h1 = __float2bfloat16(v.y);
    __nv_bfloat16 h2 = __float2bfloat16(v.z), h3 = __float2bfloat16(v.w);
    __nv_bfloat16 l0 = __float2bfloat16(v.x - __bfloat162float(h0));
    __nv_bfloat16 l1 = __float2bfloat16(v.y - __bfloat162float(h1));
    __nv_bfloat16 l2 = __float2bfloat16(v.z - __bfloat162float(h2));
    __nv_bfloat16 l3 = __float2bfloat16(v.w - __bfloat162float(h3));
    *(uint2*)((char*)hi + sw) = make_uint2(pack_bf2(h0, h1), pack_bf2(h2, h3));
    *(uint2*)((char*)lo + sw) = make_uint2(pack_bf2(l0, l1), pack_bf2(l2, l3));
}
__device__ __forceinline__ __nv_bfloat16* planeptr(
    __nv_bfloat16* buf, int g, int s, int ki, int KT)
{
    return buf + (((size_t)g * KT + ki) * 2 + s) * PLANE;
}

// ---------------- weight prep -------------------------------------------------
__global__ void __launch_bounds__(256) prep_weights(
    const float* __restrict__ W, __nv_bfloat16* __restrict__ Wp,
    int K, int groupOffset)
{
    const int g = blockIdx.x, ki = blockIdx.y;
    const int KT = K >> 6;
    const int t = threadIdx.x;
    const int r = t >> 1, c0 = (t & 1) * 32;
    __nv_bfloat16* hi = planeptr(Wp, groupOffset + g, 0, ki, KT);
    __nv_bfloat16* lo = planeptr(Wp, groupOffset + g, 1, ki, KT);
    const float* src = W + (size_t)(g * 128 + r) * K + ki * 64;
    #pragma unroll
    for (int i = 0; i < 8; i++) {
        int c = c0 + i * 4;
        store_hl8(hi, lo, r, c, *(const float4*)(src + c));
    }
}

// fused qkv weight prep: groups 0-3 <- w_q, 4-7 <- w_k, 8-11 <- w_v (K=512)
__global__ void __launch_bounds__(256) prep_qkv(
    const float* __restrict__ Wq, const float* __restrict__ Wk,
    const float* __restrict__ Wv, __nv_bfloat16* __restrict__ Wp)
{
    const int g = blockIdx.x, ki = blockIdx.y;     // g 0..11, ki 0..7
    const int t = threadIdx.x;
    const int r = t >> 1, c0 = (t & 1) * 32;
    const float* W = (g < 4) ? Wq : (g < 8) ? Wk : Wv;
    const int gl = g & 3;
    __nv_bfloat16* hi = planeptr(Wp, g, 0, ki, 8);
    __nv_bfloat16* lo = planeptr(Wp, g, 1, ki, 8);
    const float* src = W + (size_t)(gl * 128 + r) * CC + ki * 64;
    #pragma unroll
    for (int i = 0; i < 8; i++) {
        int c = c0 + i * 4;
        store_hl8(hi, lo, r, c, *(const float4*)(src + c));
    }
}

// ---------------- LayerNorm (+roll) -> packed planes (KT=8) -------------------
__global__ void __launch_bounds__(128) ln_kernel(
    const float* __restrict__ x, __nv_bfloat16* __restrict__ outp,
    const float* __restrict__ g, const float* __restrict__ b, int rolled)
{
    int row = blockIdx.x;
    int bt  = row >> 12, l = row & (LL - 1);
    int src = rolled ? ((bt << 12) | ((l + SHIFT) & (LL - 1))) : row;
    const float* xr = x + (size_t)src * CC;

    int t = threadIdx.x;
    float4 v = *(const float4*)(xr + t * 4);
    float s  = v.x + v.y + v.z + v.w;
    float ss = v.x*v.x + v.y*v.y + v.z*v.z + v.w*v.w;
    #pragma unroll
    for (int o = 16; o > 0; o >>= 1) {
        s  += __shfl_xor_sync(0xffffffffu, s,  o);
        ss += __shfl_xor_sync(0xffffffffu, ss, o);
    }
    __shared__ float red[8];
    int wid = t >> 5, lid = t & 31;
    if (lid == 0) { red[wid] = s; red[4 + wid] = ss; }
    __syncthreads();
    s  = red[0] + red[1] + red[2] + red[3];
    ss = red[4] + red[5] + red[6] + red[7];
    float mean = s * (1.0f / CC);
    float rstd = rsqrtf(ss * (1.0f / CC) - mean * mean + 1e-5f);

    float4 gg = *(const float4*)(g + t * 4);
    float4 bb = *(const float4*)(b + t * 4);
    float4 o4;
    o4.x = (v.x - mean) * rstd * gg.x + bb.x;
    o4.y = (v.y - mean) * rstd * gg.y + bb.y;
    o4.z = (v.z - mean) * rstd * gg.z + bb.z;
    o4.w = (v.w - mean) * rstd * gg.w + bb.w;

    int mi = row >> 7, r = row & 127;
    int ki = t >> 4, cc = (4 * t) & 63;
    store_hl8(planeptr(outp, mi, 0, ki, 8), planeptr(outp, mi, 1, ki, 8), r, cc, o4);
}

// ---------------- async-feed bf16x3 mma.sync GEMM -----------------------------
__device__ __forceinline__ uint32_t cvta_smem(const void* p) {
    return (uint32_t)__cvta_generic_to_shared(p);
}
__device__ __forceinline__ void ldsm4(uint32_t* r, uint32_t addr) {
    asm volatile("ldmatrix.sync.aligned.m8n8.x4.shared.b16 {%0,%1,%2,%3}, [%4];"
        : "=r"(r[0]), "=r"(r[1]), "=r"(r[2]), "=r"(r[3]) : "r"(addr));
}
__device__ __forceinline__ void mma16816(float* c, const uint32_t* a, const uint32_t* b) {
    asm volatile("mma.sync.aligned.m16n8k16.row.col.f32.bf16.bf16.f32 "
        "{%0,%1,%2,%3},{%4,%5,%6,%7},{%8,%9},{%0,%1,%2,%3};"
        : "+f"(c[0]), "+f"(c[1]), "+f"(c[2]), "+f"(c[3])
        : "r"(a[0]), "r"(a[1]), "r"(a[2]), "r"(a[3]), "r"(b[0]), "r"(b[1]));
}
__device__ __forceinline__ void mbar_init(uint32_t a, uint32_t c) {
    asm volatile("mbarrier.init.shared.b64 [%0], %1;" :: "r"(a), "r"(c) : "memory");
}
__device__ __forceinline__ void mbar_expect_tx(uint32_t a, uint32_t bytes) {
    asm volatile("mbarrier.arrive.expect_tx.shared.b64 _, [%0], %1;"
                 :: "r"(a), "r"(bytes) : "memory");
}
__device__ __forceinline__ void mbar_arrive(uint32_t a) {
    asm volatile("mbarrier.arrive.shared.b64 _, [%0];" :: "r"(a) : "memory");
}
__device__ __forceinline__ void mbar_wait(uint32_t a, uint32_t p) {
    asm volatile(
        "{\n\t.reg .pred P;\n\tLW%=:\n\t"
        "mbarrier.try_wait.parity.acquire.cta.shared::cta.b64 P, [%0], %1;\n\t"
        "@!P bra LW%=;\n\t}" :: "r"(a), "r"(p) : "memory");
}
__device__ __forceinline__ void bulk_cp(uint32_t dst, const void* src,
                                        uint32_t bytes, uint32_t mbar) {
    asm volatile(
        "cp.async.bulk.shared::cluster.global.mbarrier::complete_tx::bytes "
        "[%0], [%1], %2, [%3];"
        :: "r"(dst), "l"(src), "r"(bytes), "r"(mbar) : "memory");
}
__device__ __forceinline__ uint32_t segaddr(uint32_t base, int r, int kc) {
    return base + r * 128 + ((((kc >> 3) ^ (r & 7)) & 7) << 4);
}

#define SBYTES 98304u   // Ah|Al | B0h|B0l | B1h|B1l

// MODE 0: qkv split  1: roll+residual  2: +bias GELU  3: +bias+addsrc
template<int MODE>
__global__ void __launch_bounds__(288) tc_gemm(
    const __nv_bfloat16* __restrict__ Ap, const __nv_bfloat16* __restrict__ Bp,
    float* __restrict__ O0, float* __restrict__ O1, float* __restrict__ O2,
    const float* __restrict__ bias, const float* __restrict__ addsrc,
    int KT, int Ntot)
{
    extern __shared__ char dsm[];
    __shared__ __align__(8) uint64_t s_mbar[4];   // full0 full1 empty0 empty1

    const uint32_t sb  = (cvta_smem(dsm) + 1023u) & ~1023u;
    const uint32_t mbF = cvta_smem(&s_mbar[0]);
    const uint32_t mbE = cvta_smem(&s_mbar[2]);
    const int tid = threadIdx.x;
    const int wid = tid >> 5, lane = tid & 31;
    const int ni = blockIdx.x, mi = blockIdx.y;

    if (tid == 0) {
        mbar_init(mbF, 1); mbar_init(mbF + 8, 1);
        mbar_init(mbE, 8); mbar_init(mbE + 8, 8);
        asm volatile("fence.proxy.async.shared::cta;" ::: "memory");
    }
    __syncthreads();

    if (wid == 8) {
        // ---- producer warp ----
        if (lane == 0) {
            for (int s = 0; s < KT; s++) {
                if (s >= 2) mbar_wait(mbE + (s & 1) * 8, (uint32_t)(((s - 2) >> 1) & 1));
                int b = s & 1;
                uint32_t d = sb + b * SBYTES;
                uint32_t m = mbF + b * 8;
                mbar_expect_tx(m, SBYTES);
                bulk_cp(d,         Ap + (((size_t)mi       * KT + s) * 2) * PLANE, 32768, m);
                bulk_cp(d + 32768, Bp + (((size_t)(2*ni)   * KT + s) * 2) * PLANE, 32768, m);
                bulk_cp(d + 65536, Bp + (((size_t)(2*ni+1) * KT + s) * 2) * PLANE, 32768, m);
            }
        }
        return;
    }

    // ---- consumer warps (0-7) ----
    const int wm = (wid & 1) * 64;
    const int wn = (wid >> 1) * 64;

    float acc[4][8][4];
    #pragma unroll
    for (int a = 0; a < 4; a++)
        #pragma unroll
        for (int b = 0; b < 8; b++)
            #pragma unroll
            for (int c = 0; c < 4; c++) acc[a][b][c] = 0.0f;

    const int bplane = (wn >> 7);
    const int wnl = wn & 127;
    const int arow0 = wm + (lane & 15);
    const int akc0  = (lane >> 4) * 8;
    const int brow0 = wnl + ((lane >> 4) & 1) * 8 + (lane & 7);
    const int bkc0  = ((lane >> 3) & 1) * 8;

    for (int s = 0; s < KT; s++) {
        int b = s & 1;
        mbar_wait(mbF + b * 8, (uint32_t)((s >> 1) & 1));
        const uint32_t Ah = sb + b * SBYTES;
        const uint32_t Al = Ah + 16384;
        const uint32_t Bh = Ah + 32768 + bplane * 32768;
        const uint32_t Bl = Bh + 16384;

        #pragma unroll
        for (int kf = 0; kf < 4; kf++) {
            const int k0 = kf * 16;
            uint32_t fa[4][4], fal[4][4], fb[4][4];
            const int akc = k0 + akc0;
            const int bkc = k0 + bkc0;
            #pragma unroll
            for (int mt = 0; mt < 4; mt++)
                ldsm4(fa[mt], segaddr(Ah, arow0 + mt * 16, akc));
            #pragma unroll
            for (int j = 0; j < 4; j++)
                ldsm4(fb[j], segaddr(Bh, brow0 + j * 16, bkc));
            #pragma unroll
            for (int mt = 0; mt < 4; mt++)
                #pragma unroll
                for (int j = 0; j < 4; j++) {
                    mma16816(acc[mt][2*j],   fa[mt], &fb[j][0]);
                    mma16816(acc[mt][2*j+1], fa[mt], &fb[j][2]);
                }
            #pragma unroll
            for (int mt = 0; mt < 4; mt++)
                ldsm4(fal[mt], segaddr(Al, arow0 + mt * 16, akc));
            #pragma unroll
            for (int mt = 0; mt < 4; mt++)
                #pragma unroll
                for (int j = 0; j < 4; j++) {
                    mma16816(acc[mt][2*j],   fal[mt], &fb[j][0]);
                    mma16816(acc[mt][2*j+1], fal[mt], &fb[j][2]);
                }
            #pragma unroll
            for (int j = 0; j < 4; j++)
                ldsm4(fb[j], segaddr(Bl, brow0 + j * 16, bkc));
            // stage buffer fully read after the final ldsm batch: release early
            if (kf == 3 && lane == 0) mbar_arrive(mbE + b * 8);
            #pragma unroll
            for (int mt = 0; mt < 4; mt++)
                #pragma unroll
                for (int j = 0; j < 4; j++) {
                    mma16816(acc[mt][2*j],   fa[mt], &fb[j][0]);
                    mma16816(acc[mt][2*j+1], fa[mt], &fb[j][2]);
                }
        }
    }

    // epilogue
    const int rb = mi * 128 + wm + (lane >> 2);
    const int cb = wn + (lane & 3) * 2;
    #pragma unroll
    for (int mt = 0; mt < 4; mt++) {
        #pragma unroll
        for (int half = 0; half < 2; half++) {
            const int m = rb + mt * 16 + half * 8;
            #pragma unroll
            for (int nt = 0; nt < 8; nt++) {
                const int n = ni * 256 + cb + nt * 8;
                float v0 = acc[mt][nt][half * 2 + 0];
                float v1 = acc[mt][nt][half * 2 + 1];
                if (MODE == 0) {
                    int buf = n >> 9, col = n & 511;
                    float* dst = (buf == 0 ? O0 : (buf == 1 ? O1 : O2));
                    *(float2*)(dst + (size_t)m * CC + col) = make_float2(v0, v1);
                } else if (MODE == 1) {
                    int bt = m >> 12, l = m & (LL - 1);
                    size_t mrow = ((size_t)(bt << 12) | ((l + SHIFT) & (LL - 1)));
                    float2 r0 = *(const float2*)(addsrc + mrow * Ntot + n);
                    *(float2*)(O0 + mrow * Ntot + n) = make_float2(v0 + r0.x, v1 + r0.y);
                } else if (MODE == 2) {
                    float2 b2 = *(const float2*)(bias + n);
                    *(float2*)(O0 + (size_t)m * Ntot + n) =
                        make_float2(gelu_f(v0 + b2.x), gelu_f(v1 + b2.y));
                } else {
                    float2 b2 = *(const float2*)(bias + n);
                    float2 r0 = *(const float2*)(addsrc + (size_t)m * Ntot + n);
                    *(float2*)(O0 + (size_t)m * Ntot + n) =
                        make_float2(v0 + b2.x + r0.x, v1 + b2.y + r0.y);
                }
            }
        }
    }
}

// ---------------- window attention: 4x4 microtile version ---------------------
#define ATT_SQ   0
#define ATT_SK   (64*68)
#define ATT_SV   (ATT_SK + 64*64)
#define ATT_SB   (ATT_SV + 64*64)
#define ATT_SMEM ((ATT_SB + 128) * 4)

__global__ void __launch_bounds__(256) attn_kernel(
    const float* __restrict__ q, const float* __restrict__ k, const float* __restrict__ v,
    const float* __restrict__ rel_table,
    float* __restrict__ attn_out, __nv_bfloat16* __restrict__ ctxp, int write_attn)
{
    extern __shared__ float smf[];
    float* sQ = smf + ATT_SQ;
    float* sK = smf + ATT_SK;
    float* sV = smf + ATT_SV;
    float* sB = smf + ATT_SB;

    const int h = blockIdx.x;
    const int w = blockIdx.y;
    const int tid = threadIdx.x;
    const size_t base = (size_t)w * WSZ * CC + (size_t)h * DK;

    {
        int t = tid >> 2, qd = tid & 3;
        #pragma unroll
        for (int i = 0; i < 4; i++) {
            int d0 = qd * 16 + i * 4;
            float4 qv = *(const float4*)(q + base + (size_t)t * CC + d0);
            sQ[(d0+0)*68 + t] = qv.x; sQ[(d0+1)*68 + t] = qv.y;
            sQ[(d0+2)*68 + t] = qv.z; sQ[(d0+3)*68 + t] = qv.w;
            float4 kv = *(const float4*)(k + base + (size_t)t * CC + d0);
            sK[(d0+0)*64 + t] = kv.x; sK[(d0+1)*64 + t] = kv.y;
            sK[(d0+2)*64 + t] = kv.z; sK[(d0+3)*64 + t] = kv.w;
            float4 vv = *(const float4*)(v + base + (size_t)t * CC + d0);
            *(float4*)(sV + t * 64 + d0) = vv;
        }
        if (tid < 127) sB[tid] = rel_table[tid * NH + h];
    }
    __syncthreads();

    const int ty = tid >> 4, tx = tid & 15;
    float sc[4][4];
    #pragma unroll
    for (int i = 0; i < 4; i++)
        #pragma unroll
        for (int j = 0; j < 4; j++) sc[i][j] = 0.0f;

    #pragma unroll 8
    for (int d = 0; d < 64; d++) {
        float4 qv = *(const float4*)(sQ + d * 68 + ty * 4);
        float4 kv = *(const float4*)(sK + d * 64 + tx * 4);
        float qa[4] = {qv.x, qv.y, qv.z, qv.w};
        float ka[4] = {kv.x, kv.y, kv.z, kv.w};
        #pragma unroll
        for (int i = 0; i < 4; i++)
            #pragma unroll
            for (int j = 0; j < 4; j++)
                sc[i][j] += qa[i] * ka[j];
    }

    const bool last = ((w & (NW - 1)) == (NW - 1));
    #pragma unroll
    for (int i = 0; i < 4; i++) {
        int t = ty * 4 + i;
        #pragma unroll
        for (int j = 0; j < 4; j++) {
            int t2 = tx * 4 + j;
            float s = sc[i][j] * 0.125f + sB[t - t2 + 63];
            if (last && ((t < 32) != (t2 < 32))) s -= 100.0f;
            sc[i][j] = s;
        }
    }

    #pragma unroll
    for (int i = 0; i < 4; i++) {
        float m = fmaxf(fmaxf(sc[i][0], sc[i][1]), fmaxf(sc[i][2], sc[i][3]));
        m = fmaxf(m, __shfl_xor_sync(0xffffffffu, m, 1));
        m = fmaxf(m, __shfl_xor_sync(0xffffffffu, m, 2));
        m = fmaxf(m, __shfl_xor_sync(0xffffffffu, m, 4));
        m = fmaxf(m, __shfl_xor_sync(0xffffffffu, m, 8));
        float s = 0.0f;
        #pragma unroll
        for (int j = 0; j < 4; j++) { sc[i][j] = __expf(sc[i][j] - m); s += sc[i][j]; }
        s += __shfl_xor_sync(0xffffffffu, s, 1);
        s += __shfl_xor_sync(0xffffffffu, s, 2);
        s += __shfl_xor_sync(0xffffffffu, s, 4);
        s += __shfl_xor_sync(0xffffffffu, s, 8);
        float inv = 1.0f / s;
        #pragma unroll
        for (int j = 0; j < 4; j++) sc[i][j] *= inv;
    }

    if (write_attn) {
        #pragma unroll
        for (int i = 0; i < 4; i++) {
            int t = ty * 4 + i;
            size_t ao = ((((size_t)w * NH + h) * WSZ) + t) * WSZ + tx * 4;
            *(float4*)(attn_out + ao) = make_float4(sc[i][0], sc[i][1], sc[i][2], sc[i][3]);
        }
    }

    __syncthreads();
    #pragma unroll
    for (int i = 0; i < 4; i++) {
        int t = ty * 4 + i;
        #pragma unroll
        for (int j = 0; j < 4; j++)
            sQ[(tx * 4 + j) * 68 + t] = sc[i][j];
    }
    __syncthreads();

    float oa[4][4];
    #pragma unroll
    for (int i = 0; i < 4; i++)
        #pragma unroll
        for (int j = 0; j < 4; j++) oa[i][j] = 0.0f;

    #pragma unroll 8
    for (int t2 = 0; t2 < 64; t2++) {
        float4 sv = *(const float4*)(sQ + t2 * 68 + ty * 4);
        float4 vv = *(const float4*)(sV + t2 * 64 + tx * 4);
        float sa[4] = {sv.x, sv.y, sv.z, sv.w};
        float va[4] = {vv.x, vv.y, vv.z, vv.w};
        #pragma unroll
        for (int i = 0; i < 4; i++)
            #pragma unroll
            for (int j = 0; j < 4; j++)
                oa[i][j] += sa[i] * va[j];
    }

    #pragma unroll
    for (int i = 0; i < 4; i++) {
        int gr = w * WSZ + ty * 4 + i;
        int mi = gr >> 7, r = gr & 127;
        store_hl8(planeptr(ctxp, mi, 0, h, 8), planeptr(ctxp, mi, 1, h, 8),
                  r, tx * 4, make_float4(oa[i][0], oa[i][1], oa[i][2], oa[i][3]));
    }
}

// ---------------- dwconv (k=3) + GELU -> packed planes (KT=32) ----------------
__global__ void __launch_bounds__(256) dwconv_kernel(
    const float* __restrict__ f, const float* __restrict__ c2w,
    const float* __restrict__ c2b, __nv_bfloat16* __restrict__ outp)
{
    size_t idx = (size_t)blockIdx.x * blockDim.x + threadIdx.x;
    if (idx >= (size_t)TOK * HID / 4) return;
    size_t e = idx * 4;
    int ch = (int)(e % HID);
    size_t row = e / HID;
    int l = (int)(row & (LL - 1));

    float4 fc = *(const float4*)(f + e);
    float4 fm = make_float4(0.f, 0.f, 0.f, 0.f);
    float4 fp = make_float4(0.f, 0.f, 0.f, 0.f);
    if (l > 0)      fm = *(const float4*)(f + e - HID);
    if (l < LL - 1) fp = *(const float4*)(f + e + HID);

    float rr[4];
    float fmv[4] = {fm.x, fm.y, fm.z, fm.w};
    float fcv[4] = {fc.x, fc.y, fc.z, fc.w};
    float fpv[4] = {fp.x, fp.y, fp.z, fp.w};
    #pragma unroll
    for (int j = 0; j < 4; j++) {
        int c = ch + j;
        float dw = fmv[j] * c2w[c*3+0] + fcv[j] * c2w[c*3+1] + fpv[j] * c2w[c*3+2] + c2b[c];
        rr[j] = gelu_f(dw + fcv[j]);
    }
    int mi = (int)(row >> 7), r = (int)(row & 127);
    int ki = ch >> 6, cc = ch & 63;
    store_hl8(planeptr(outp, mi, 0, ki, 32), planeptr(outp, mi, 1, ki, 32),
              r, cc, make_float4(rr[0], rr[1], rr[2], rr[3]));
}

// ---------------- launch ------------------------------------------------------
extern "C" void kernel_launch(void* const* d_in, const int* in_sizes, int n_in,
                              void* d_out, int out_size)
{
    const float* x      = (const float*)d_in[0];
    const float* ln1_g  = (const float*)d_in[1];
    const float* ln1_b  = (const float*)d_in[2];
    const float* w_q    = (const float*)d_in[3];
    const float* w_k    = (const float*)d_in[4];
    const float* w_v    = (const float*)d_in[5];
    const float* w_o    = (const float*)d_in[6];
    const float* rel    = (const float*)d_in[7];
    const float* ln2_g  = (const float*)d_in[8];
    const float* ln2_b  = (const float*)d_in[9];
    const float* c1_w   = (const float*)d_in[10];
    const float* c1_b   = (const float*)d_in[11];
    const float* c2_w   = (const float*)d_in[12];
    const float* c2_b   = (const float*)d_in[13];
    const float* c3_w   = (const float*)d_in[14];
    const float* c3_b   = (const float*)d_in[15];
    float* out = (float*)d_out;

    __nv_bfloat16 *hp, *ctxp, *f2p, *wqkvp, *wop, *c1wp, *c3wp;
    float *q, *k, *v, *f;
    cudaGetSymbolAddress((void**)&hp,    g_hp);
    cudaGetSymbolAddress((void**)&ctxp,  g_ctxp);
    cudaGetSymbolAddress((void**)&f2p,   g_f2p);
    cudaGetSymbolAddress((void**)&wqkvp, g_wqkvp);
    cudaGetSymbolAddress((void**)&wop,   g_wop);
    cudaGetSymbolAddress((void**)&c1wp,  g_c1wp);
    cudaGetSymbolAddress((void**)&c3wp,  g_c3wp);
    cudaGetSymbolAddress((void**)&q, g_q);
    cudaGetSymbolAddress((void**)&k, g_k);
    cudaGetSymbolAddress((void**)&v, g_v);
    cudaGetSymbolAddress((void**)&f, g_f);
    float* y1 = q;

    const int write_attn = ((size_t)out_size >= Y_ELEMS + ATTN_ELEMS) ? 1 : 0;
    float* attn_out = out + Y_ELEMS;

    const int dyn = 2 * SBYTES + 1024;
    cudaFuncSetAttribute(tc_gemm<0>, cudaFuncAttributeMaxDynamicSharedMemorySize, dyn);
    cudaFuncSetAttribute(tc_gemm<1>, cudaFuncAttributeMaxDynamicSharedMemorySize, dyn);
    cudaFuncSetAttribute(tc_gemm<2>, cudaFuncAttributeMaxDynamicSharedMemorySize, dyn);
    cudaFuncSetAttribute(tc_gemm<3>, cudaFuncAttributeMaxDynamicSharedMemorySize, dyn);
    cudaFuncSetAttribute(attn_kernel, cudaFuncAttributeMaxDynamicSharedMemorySize, ATT_SMEM);

    // Harness prepends 2 launches (observed: my idx 3 == ncu's -s 5 capture).
    // Keep tc_gemm<0> at MY index 3 so next profile captures the hot GEMM.
    prep_qkv<<<dim3(12, 8), 256>>>(w_q, w_k, w_v, wqkvp);     // my 0
    ln_kernel<<<TOK, 128>>>(x, hp, ln1_g, ln1_b, 1);          // my 1
    prep_weights<<<dim3(4, 8), 256>>>(w_o, wop, CC, 0);       // my 2

    tc_gemm<0><<<dim3(6, TOK/128), 288, dyn>>>(hp, wqkvp, q, k, v,
                                               nullptr, nullptr, 8, 1536);  // my 3

    attn_kernel<<<dim3(NH, BB*NW), 256, ATT_SMEM>>>(q, k, v, rel, attn_out, ctxp, write_attn);

    tc_gemm<1><<<dim3(2, TOK/128), 288, dyn>>>(ctxp, wop, y1, nullptr, nullptr,
                                               nullptr, x, 8, CC);

    ln_kernel<<<TOK, 128>>>(y1, hp, ln2_g, ln2_b, 0);

    prep_weights<<<dim3(16, 8), 256>>>(c1_w, c1wp, CC, 0);
    tc_gemm<2><<<dim3(8, TOK/128), 288, dyn>>>(hp, c1wp, f, nullptr, nullptr,
                                               c1_b, nullptr, 8, HID);

    size_t nthread = (size_t)TOK * HID / 4;
    dwconv_kernel<<<(unsigned)((nthread + 255) / 256), 256>>>(f, c2_w, c2_b, f2p);

    prep_weights<<<dim3(4, 32), 256>>>(c3_w, c3wp, HID, 0);
    tc_gemm<3><<<dim3(2, TOK/128), 288, dyn>>>(f2p, c3wp, out, nullptr, nullptr,
                                               c3_b, y1, 32, CC);
}

// round 12
// speedup vs baseline: 1.0209x; 1.0183x over previous
#include <cuda_runtime.h>
#include <cuda_bf16.h>
#include <math.h>
#include <stdint.h>

#define BB   32
#define LL   4096
#define CC   512
#define WSZ  64
#define SHIFT 32
#define NH   8
#define DK   64
#define HID  2048
#define NW   64
#define TOK  (BB*LL)
#define Y_ELEMS   ((size_t)TOK*CC)
#define ATTN_ELEMS ((size_t)BB*NW*NH*WSZ*WSZ)
#define PLANE 8192              // elements per 128x64 bf16 plane (16KB)

// ---------------- scratch ----------------------------------------------------
// packed layout: group g, k-plane ki, split s(0=hi,1=lo):
//   offset = ((g*KT + ki)*2 + s) * PLANE       (hi/lo adjacent -> 32KB TMA)
__device__ __nv_bfloat16 g_hp   [(size_t)TOK*2*CC];
__device__ __nv_bfloat16 g_ctxp [(size_t)TOK*2*CC];
__device__ __nv_bfloat16 g_f2p  [(size_t)TOK*2*HID];
__device__ __nv_bfloat16 g_wqkvp[(size_t)(3*CC)*2*CC];
__device__ __nv_bfloat16 g_wop  [(size_t)CC*2*CC];
__device__ __nv_bfloat16 g_c1wp [(size_t)HID*2*CC];
__device__ __nv_bfloat16 g_c3wp [(size_t)CC*2*HID];
__device__ float g_q[(size_t)TOK*CC];   // q; reused as y1
__device__ float g_k[(size_t)TOK*CC];
__device__ float g_v[(size_t)TOK*CC];
__device__ float g_f[(size_t)TOK*HID];  // c1 out fp32

__device__ __forceinline__ float gelu_f(float x) {
    return 0.5f * x * (1.0f + erff(x * 0.70710678118654752440f));
}
__device__ __forceinline__ uint32_t pack_bf2(__nv_bfloat16 a, __nv_bfloat16 b) {
    return (uint32_t)__bfloat16_as_ushort(a) | ((uint32_t)__bfloat16_as_ushort(b) << 16);
}
__device__ __forceinline__ void store_hl8(
    __nv_bfloat16* hi, __nv_bfloat16* lo, int r, int cc, float4 v)
{
    int off = r * 128 + cc * 2;
    int sw  = off ^ ((off >> 3) & 0x70);
    __nv_bfloat16 h0 = __float2bfloat16(v.x), h1 = __float2bfloat16(v.y);
    __nv_bfloat16 h2 = __float2bfloat16(v.z), h3 = __float2bfloat16(v.w);
    __nv_bfloat16 l0 = __float2bfloat16(v.x - __bfloat162float(h0));
    __nv_bfloat16 l1 = __float2bfloat16(v.y - __bfloat162float(h1));
    __nv_bfloat16 l2 = __float2bfloat16(v.z - __bfloat162float(h2));
    __nv_bfloat16 l3 = __float2bfloat16(v.w - __bfloat162float(h3));
    *(uint2*)((char*)hi + sw) = make_uint2(pack_bf2(h0, h1), pack_bf2(h2, h3));
    *(uint2*)((char*)lo + sw) = make_uint2(pack_bf2(l0, l1), pack_bf2(l2, l3));
}
__device__ __forceinline__ __nv_bfloat16* planeptr(
    __nv_bfloat16* buf, int g, int s, int ki, int KT)
{
    return buf + (((size_t)g * KT + ki) * 2 + s) * PLANE;
}

// ---------------- weight prep -------------------------------------------------
__global__ void __launch_bounds__(256) prep_weights(
    const float* __restrict__ W, __nv_bfloat16* __restrict__ Wp,
    int K, int groupOffset)
{
    const int g = blockIdx.x, ki = blockIdx.y;
    const int KT = K >> 6;
    const int t = threadIdx.x;
    const int r = t >> 1, c0 = (t & 1) * 32;
    __nv_bfloat16* hi = planeptr(Wp, groupOffset + g, 0, ki, KT);
    __nv_bfloat16* lo = planeptr(Wp, groupOffset + g, 1, ki, KT);
    const float* src = W + (size_t)(g * 128 + r) * K + ki * 64;
    #pragma unroll
    for (int i = 0; i < 8; i++) {
        int c = c0 + i * 4;
        store_hl8(hi, lo, r, c, *(const float4*)(src + c));
    }
}

// fused qkv weight prep: groups 0-3 <- w_q, 4-7 <- w_k, 8-11 <- w_v (K=512)
__global__ void __launch_bounds__(256) prep_qkv(
    const float* __restrict__ Wq, const float* __restrict__ Wk,
    const float* __restrict__ Wv, __nv_bfloat16* __restrict__ Wp)
{
    const int g = blockIdx.x, ki = blockIdx.y;     // g 0..11, ki 0..7
    const int t = threadIdx.x;
    const int r = t >> 1, c0 = (t & 1) * 32;
    const float* W = (g < 4) ? Wq : (g < 8) ? Wk : Wv;
    const int gl = g & 3;
    __nv_bfloat16* hi = planeptr(Wp, g, 0, ki, 8);
    __nv_bfloat16* lo = planeptr(Wp, g, 1, ki, 8);
    const float* src = W + (size_t)(gl * 128 + r) * CC + ki * 64;
    #pragma unroll
    for (int i = 0; i < 8; i++) {
        int c = c0 + i * 4;
        store_hl8(hi, lo, r, c, *(const float4*)(src + c));
    }
}

// ---------------- LayerNorm (+roll) -> packed planes (KT=8) -------------------
__global__ void __launch_bounds__(128) ln_kernel(
    const float* __restrict__ x, __nv_bfloat16* __restrict__ outp,
    const float* __restrict__ g, const float* __restrict__ b, int rolled)
{
    int row = blockIdx.x;
    int bt  = row >> 12, l = row & (LL - 1);
    int src = rolled ? ((bt << 12) | ((l + SHIFT) & (LL - 1))) : row;
    const float* xr = x + (size_t)src * CC;

    int t = threadIdx.x;
    float4 v = *(const float4*)(xr + t * 4);
    float s  = v.x + v.y + v.z + v.w;
    float ss = v.x*v.x + v.y*v.y + v.z*v.z + v.w*v.w;
    #pragma unroll
    for (int o = 16; o > 0; o >>= 1) {
        s  += __shfl_xor_sync(0xffffffffu, s,  o);
        ss += __shfl_xor_sync(0xffffffffu, ss, o);
    }
    __shared__ float red[8];
    int wid = t >> 5, lid = t & 31;
    if (lid == 0) { red[wid] = s; red[4 + wid] = ss; }
    __syncthreads();
    s  = red[0] + red[1] + red[2] + red[3];
    ss = red[4] + red[5] + red[6] + red[7];
    float mean = s * (1.0f / CC);
    float rstd = rsqrtf(ss * (1.0f / CC) - mean * mean + 1e-5f);

    float4 gg = *(const float4*)(g + t * 4);
    float4 bb = *(const float4*)(b + t * 4);
    float4 o4;
    o4.x = (v.x - mean) * rstd * gg.x + bb.x;
    o4.y = (v.y - mean) * rstd * gg.y + bb.y;
    o4.z = (v.z - mean) * rstd * gg.z + bb.z;
    o4.w = (v.w - mean) * rstd * gg.w + bb.w;

    int mi = row >> 7, r = row & 127;
    int ki = t >> 4, cc = (4 * t) & 63;
    store_hl8(planeptr(outp, mi, 0, ki, 8), planeptr(outp, mi, 1, ki, 8), r, cc, o4);
}

// ---------------- async-feed bf16x3 mma.sync GEMM (persistent CTAs) ----------
__device__ __forceinline__ uint32_t cvta_smem(const void* p) {
    return (uint32_t)__cvta_generic_to_shared(p);
}
__device__ __forceinline__ void ldsm4(uint32_t* r, uint32_t addr) {
    asm volatile("ldmatrix.sync.aligned.m8n8.x4.shared.b16 {%0,%1,%2,%3}, [%4];"
        : "=r"(r[0]), "=r"(r[1]), "=r"(r[2]), "=r"(r[3]) : "r"(addr));
}
__device__ __forceinline__ void mma16816(float* c, const uint32_t* a, const uint32_t* b) {
    asm volatile("mma.sync.aligned.m16n8k16.row.col.f32.bf16.bf16.f32 "
        "{%0,%1,%2,%3},{%4,%5,%6,%7},{%8,%9},{%0,%1,%2,%3};"
        : "+f"(c[0]), "+f"(c[1]), "+f"(c[2]), "+f"(c[3])
        : "r"(a[0]), "r"(a[1]), "r"(a[2]), "r"(a[3]), "r"(b[0]), "r"(b[1]));
}
__device__ __forceinline__ void mbar_init(uint32_t a, uint32_t c) {
    asm volatile("mbarrier.init.shared.b64 [%0], %1;" :: "r"(a), "r"(c) : "memory");
}
__device__ __forceinline__ void mbar_expect_tx(uint32_t a, uint32_t bytes) {
    asm volatile("mbarrier.arrive.expect_tx.shared.b64 _, [%0], %1;"
                 :: "r"(a), "r"(bytes) : "memory");
}
__device__ __forceinline__ void mbar_arrive(uint32_t a) {
    asm volatile("mbarrier.arrive.shared.b64 _, [%0];" :: "r"(a) : "memory");
}
__device__ __forceinline__ void mbar_wait(uint32_t a, uint32_t p) {
    asm volatile(
        "{\n\t.reg .pred P;\n\tLW%=:\n\t"
        "mbarrier.try_wait.parity.acquire.cta.shared::cta.b64 P, [%0], %1;\n\t"
        "@!P bra LW%=;\n\t}" :: "r"(a), "r"(p) : "memory");
}
__device__ __forceinline__ void bulk_cp(uint32_t dst, const void* src,
                                        uint32_t bytes, uint32_t mbar) {
    asm volatile(
        "cp.async.bulk.shared::cluster.global.mbarrier::complete_tx::bytes "
        "[%0], [%1], %2, [%3];"
        :: "r"(dst), "l"(src), "r"(bytes), "r"(mbar) : "memory");
}
__device__ __forceinline__ uint32_t segaddr(uint32_t base, int r, int kc) {
    return base + r * 128 + ((((kc >> 3) ^ (r & 7)) & 7) << 4);
}

#define SBYTES 98304u   // Ah|Al | B0h|B0l | B1h|B1l

// MODE 0: qkv split  1: roll+residual  2: +bias GELU  3: +bias+addsrc
// Persistent: grid = numSM; each CTA strides over (mi, ni) tiles; the 2-deep
// TMA ring runs on a GLOBAL stage counter so prologue/epilogue of successive
// tiles overlap with the async feed.
template<int MODE>
__global__ void __launch_bounds__(288) tc_gemm(
    const __nv_bfloat16* __restrict__ Ap, const __nv_bfloat16* __restrict__ Bp,
    float* __restrict__ O0, float* __restrict__ O1, float* __restrict__ O2,
    const float* __restrict__ bias, const float* __restrict__ addsrc,
    int KT, int Ntot, int NTX, int ntiles)
{
    extern __shared__ char dsm[];
    __shared__ __align__(8) uint64_t s_mbar[4];   // full0 full1 empty0 empty1

    const uint32_t sb  = (cvta_smem(dsm) + 1023u) & ~1023u;
    const uint32_t mbF = cvta_smem(&s_mbar[0]);
    const uint32_t mbE = cvta_smem(&s_mbar[2]);
    const int tid = threadIdx.x;
    const int wid = tid >> 5, lane = tid & 31;

    if (tid == 0) {
        mbar_init(mbF, 1); mbar_init(mbF + 8, 1);
        mbar_init(mbE, 8); mbar_init(mbE + 8, 8);
        asm volatile("fence.proxy.async.shared::cta;" ::: "memory");
    }
    __syncthreads();

    if (wid == 8) {
        // ---- producer warp: continuous ring across all tiles ----
        if (lane == 0) {
            int gs = 0;
            for (int tile = blockIdx.x; tile < ntiles; tile += gridDim.x) {
                const int ni = tile % NTX, mi = tile / NTX;
                for (int s = 0; s < KT; s++, gs++) {
                    if (gs >= 2) mbar_wait(mbE + (gs & 1) * 8, (uint32_t)(((gs - 2) >> 1) & 1));
                    int b = gs & 1;
                    uint32_t d = sb + b * SBYTES;
                    uint32_t m = mbF + b * 8;
                    mbar_expect_tx(m, SBYTES);
                    bulk_cp(d,         Ap + (((size_t)mi       * KT + s) * 2) * PLANE, 32768, m);
                    bulk_cp(d + 32768, Bp + (((size_t)(2*ni)   * KT + s) * 2) * PLANE, 32768, m);
                    bulk_cp(d + 65536, Bp + (((size_t)(2*ni+1) * KT + s) * 2) * PLANE, 32768, m);
                }
            }
        }
        return;
    }

    // ---- consumer warps (0-7) ----
    const int wm = (wid & 1) * 64;
    const int wn = (wid >> 1) * 64;
    const int bplane = (wn >> 7);
    const int wnl = wn & 127;
    const int arow0 = wm + (lane & 15);
    const int akc0  = (lane >> 4) * 8;
    const int brow0 = wnl + ((lane >> 4) & 1) * 8 + (lane & 7);
    const int bkc0  = ((lane >> 3) & 1) * 8;
    const int rb0 = wm + (lane >> 2);
    const int cb  = wn + (lane & 3) * 2;

    int gs = 0;
    for (int tile = blockIdx.x; tile < ntiles; tile += gridDim.x) {
        const int ni = tile % NTX, mi = tile / NTX;

        float acc[4][8][4];
        #pragma unroll
        for (int a = 0; a < 4; a++)
            #pragma unroll
            for (int b = 0; b < 8; b++)
                #pragma unroll
                for (int c = 0; c < 4; c++) acc[a][b][c] = 0.0f;

        for (int s = 0; s < KT; s++, gs++) {
            int b = gs & 1;
            mbar_wait(mbF + b * 8, (uint32_t)((gs >> 1) & 1));
            const uint32_t Ah = sb + b * SBYTES;
            const uint32_t Al = Ah + 16384;
            const uint32_t Bh = Ah + 32768 + bplane * 32768;
            const uint32_t Bl = Bh + 16384;

            #pragma unroll
            for (int kf = 0; kf < 4; kf++) {
                const int k0 = kf * 16;
                uint32_t fa[4][4], fal[4][4], fb[4][4];
                const int akc = k0 + akc0;
                const int bkc = k0 + bkc0;
                #pragma unroll
                for (int mt = 0; mt < 4; mt++)
                    ldsm4(fa[mt], segaddr(Ah, arow0 + mt * 16, akc));
                #pragma unroll
                for (int j = 0; j < 4; j++)
                    ldsm4(fb[j], segaddr(Bh, brow0 + j * 16, bkc));
                #pragma unroll
                for (int mt = 0; mt < 4; mt++)
                    #pragma unroll
                    for (int j = 0; j < 4; j++) {
                        mma16816(acc[mt][2*j],   fa[mt], &fb[j][0]);
                        mma16816(acc[mt][2*j+1], fa[mt], &fb[j][2]);
                    }
                #pragma unroll
                for (int mt = 0; mt < 4; mt++)
                    ldsm4(fal[mt], segaddr(Al, arow0 + mt * 16, akc));
                #pragma unroll
                for (int mt = 0; mt < 4; mt++)
                    #pragma unroll
                    for (int j = 0; j < 4; j++) {
                        mma16816(acc[mt][2*j],   fal[mt], &fb[j][0]);
                        mma16816(acc[mt][2*j+1], fal[mt], &fb[j][2]);
                    }
                #pragma unroll
                for (int j = 0; j < 4; j++)
                    ldsm4(fb[j], segaddr(Bl, brow0 + j * 16, bkc));
                // stage fully read after the final ldsm batch: release early
                if (kf == 3 && lane == 0) mbar_arrive(mbE + b * 8);
                #pragma unroll
                for (int mt = 0; mt < 4; mt++)
                    #pragma unroll
                    for (int j = 0; j < 4; j++) {
                        mma16816(acc[mt][2*j],   fa[mt], &fb[j][0]);
                        mma16816(acc[mt][2*j+1], fa[mt], &fb[j][2]);
                    }
            }
        }

        // epilogue for this tile (producer already prefetching next tile)
        const int rb = mi * 128 + rb0;
        #pragma unroll
        for (int mt = 0; mt < 4; mt++) {
            #pragma unroll
            for (int half = 0; half < 2; half++) {
                const int m = rb + mt * 16 + half * 8;
                #pragma unroll
                for (int nt = 0; nt < 8; nt++) {
                    const int n = ni * 256 + cb + nt * 8;
                    float v0 = acc[mt][nt][half * 2 + 0];
                    float v1 = acc[mt][nt][half * 2 + 1];
                    if (MODE == 0) {
                        int buf = n >> 9, col = n & 511;
                        float* dst = (buf == 0 ? O0 : (buf == 1 ? O1 : O2));
                        *(float2*)(dst + (size_t)m * CC + col) = make_float2(v0, v1);
                    } else if (MODE == 1) {
                        int bt = m >> 12, l = m & (LL - 1);
                        size_t mrow = ((size_t)(bt << 12) | ((l + SHIFT) & (LL - 1)));
                        float2 r0 = *(const float2*)(addsrc + mrow * Ntot + n);
                        *(float2*)(O0 + mrow * Ntot + n) = make_float2(v0 + r0.x, v1 + r0.y);
                    } else if (MODE == 2) {
                        float2 b2 = *(const float2*)(bias + n);
                        *(float2*)(O0 + (size_t)m * Ntot + n) =
                            make_float2(gelu_f(v0 + b2.x), gelu_f(v1 + b2.y));
                    } else {
                        float2 b2 = *(const float2*)(bias + n);
                        float2 r0 = *(const float2*)(addsrc + (size_t)m * Ntot + n);
                        *(float2*)(O0 + (size_t)m * Ntot + n) =
                            make_float2(v0 + b2.x + r0.x, v1 + b2.y + r0.y);
                    }
                }
            }
        }
    }
}

// ---------------- window attention: 4x4 microtile version ---------------------
#define ATT_SQ   0
#define ATT_SK   (64*68)
#define ATT_SV   (ATT_SK + 64*64)
#define ATT_SB   (ATT_SV + 64*64)
#define ATT_SMEM ((ATT_SB + 128) * 4)

__global__ void __launch_bounds__(256) attn_kernel(
    const float* __restrict__ q, const float* __restrict__ k, const float* __restrict__ v,
    const float* __restrict__ rel_table,
    float* __restrict__ attn_out, __nv_bfloat16* __restrict__ ctxp, int write_attn)
{
    extern __shared__ float smf[];
    float* sQ = smf + ATT_SQ;
    float* sK = smf + ATT_SK;
    float* sV = smf + ATT_SV;
    float* sB = smf + ATT_SB;

    const int h = blockIdx.x;
    const int w = blockIdx.y;
    const int tid = threadIdx.x;
    const size_t base = (size_t)w * WSZ * CC + (size_t)h * DK;

    {
        int t = tid >> 2, qd = tid & 3;
        #pragma unroll
        for (int i = 0; i < 4; i++) {
            int d0 = qd * 16 + i * 4;
            float4 qv = *(const float4*)(q + base + (size_t)t * CC + d0);
            sQ[(d0+0)*68 + t] = qv.x; sQ[(d0+1)*68 + t] = qv.y;
            sQ[(d0+2)*68 + t] = qv.z; sQ[(d0+3)*68 + t] = qv.w;
            float4 kv = *(const float4*)(k + base + (size_t)t * CC + d0);
            sK[(d0+0)*64 + t] = kv.x; sK[(d0+1)*64 + t] = kv.y;
            sK[(d0+2)*64 + t] = kv.z; sK[(d0+3)*64 + t] = kv.w;
            float4 vv = *(const float4*)(v + base + (size_t)t * CC + d0);
            *(float4*)(sV + t * 64 + d0) = vv;
        }
        if (tid < 127) sB[tid] = rel_table[tid * NH + h];
    }
    __syncthreads();

    const int ty = tid >> 4, tx = tid & 15;
    float sc[4][4];
    #pragma unroll
    for (int i = 0; i < 4; i++)
        #pragma unroll
        for (int j = 0; j < 4; j++) sc[i][j] = 0.0f;

    #pragma unroll 8
    for (int d = 0; d < 64; d++) {
        float4 qv = *(const float4*)(sQ + d * 68 + ty * 4);
        float4 kv = *(const float4*)(sK + d * 64 + tx * 4);
        float qa[4] = {qv.x, qv.y, qv.z, qv.w};
        float ka[4] = {kv.x, kv.y, kv.z, kv.w};
        #pragma unroll
        for (int i = 0; i < 4; i++)
            #pragma unroll
            for (int j = 0; j < 4; j++)
                sc[i][j] += qa[i] * ka[j];
    }

    const bool last = ((w & (NW - 1)) == (NW - 1));
    #pragma unroll
    for (int i = 0; i < 4; i++) {
        int t = ty * 4 + i;
        #pragma unroll
        for (int j = 0; j < 4; j++) {
            int t2 = tx * 4 + j;
            float s = sc[i][j] * 0.125f + sB[t - t2 + 63];
            if (last && ((t < 32) != (t2 < 32))) s -= 100.0f;
            sc[i][j] = s;
        }
    }

    #pragma unroll
    for (int i = 0; i < 4; i++) {
        float m = fmaxf(fmaxf(sc[i][0], sc[i][1]), fmaxf(sc[i][2], sc[i][3]));
        m = fmaxf(m, __shfl_xor_sync(0xffffffffu, m, 1));
        m = fmaxf(m, __shfl_xor_sync(0xffffffffu, m, 2));
        m = fmaxf(m, __shfl_xor_sync(0xffffffffu, m, 4));
        m = fmaxf(m, __shfl_xor_sync(0xffffffffu, m, 8));
        float s = 0.0f;
        #pragma unroll
        for (int j = 0; j < 4; j++) { sc[i][j] = __expf(sc[i][j] - m); s += sc[i][j]; }
        s += __shfl_xor_sync(0xffffffffu, s, 1);
        s += __shfl_xor_sync(0xffffffffu, s, 2);
        s += __shfl_xor_sync(0xffffffffu, s, 4);
        s += __shfl_xor_sync(0xffffffffu, s, 8);
        float inv = 1.0f / s;
        #pragma unroll
        for (int j = 0; j < 4; j++) sc[i][j] *= inv;
    }

    if (write_attn) {
        #pragma unroll
        for (int i = 0; i < 4; i++) {
            int t = ty * 4 + i;
            size_t ao = ((((size_t)w * NH + h) * WSZ) + t) * WSZ + tx * 4;
            *(float4*)(attn_out + ao) = make_float4(sc[i][0], sc[i][1], sc[i][2], sc[i][3]);
        }
    }

    __syncthreads();
    #pragma unroll
    for (int i = 0; i < 4; i++) {
        int t = ty * 4 + i;
        #pragma unroll
        for (int j = 0; j < 4; j++)
            sQ[(tx * 4 + j) * 68 + t] = sc[i][j];
    }
    __syncthreads();

    float oa[4][4];
    #pragma unroll
    for (int i = 0; i < 4; i++)
        #pragma unroll
        for (int j = 0; j < 4; j++) oa[i][j] = 0.0f;

    #pragma unroll 8
    for (int t2 = 0; t2 < 64; t2++) {
        float4 sv = *(const float4*)(sQ + t2 * 68 + ty * 4);
        float4 vv = *(const float4*)(sV + t2 * 64 + tx * 4);
        float sa[4] = {sv.x, sv.y, sv.z, sv.w};
        float va[4] = {vv.x, vv.y, vv.z, vv.w};
        #pragma unroll
        for (int i = 0; i < 4; i++)
            #pragma unroll
            for (int j = 0; j < 4; j++)
                oa[i][j] += sa[i] * va[j];
    }

    #pragma unroll
    for (int i = 0; i < 4; i++) {
        int gr = w * WSZ + ty * 4 + i;
        int mi = gr >> 7, r = gr & 127;
        store_hl8(planeptr(ctxp, mi, 0, h, 8), planeptr(ctxp, mi, 1, h, 8),
                  r, tx * 4, make_float4(oa[i][0], oa[i][1], oa[i][2], oa[i][3]));
    }
}

// ---------------- dwconv (k=3) + GELU -> packed planes (KT=32) ----------------
__global__ void __launch_bounds__(256) dwconv_kernel(
    const float* __restrict__ f, const float* __restrict__ c2w,
    const float* __restrict__ c2b, __nv_bfloat16* __restrict__ outp)
{
    size_t idx = (size_t)blockIdx.x * blockDim.x + threadIdx.x;
    if (idx >= (size_t)TOK * HID / 4) return;
    size_t e = idx * 4;
    int ch = (int)(e % HID);
    size_t row = e / HID;
    int l = (int)(row & (LL - 1));

    float4 fc = *(const float4*)(f + e);
    float4 fm = make_float4(0.f, 0.f, 0.f, 0.f);
    float4 fp = make_float4(0.f, 0.f, 0.f, 0.f);
    if (l > 0)      fm = *(const float4*)(f + e - HID);
    if (l < LL - 1) fp = *(const float4*)(f + e + HID);

    float rr[4];
    float fmv[4] = {fm.x, fm.y, fm.z, fm.w};
    float fcv[4] = {fc.x, fc.y, fc.z, fc.w};
    float fpv[4] = {fp.x, fp.y, fp.z, fp.w};
    #pragma unroll
    for (int j = 0; j < 4; j++) {
        int c = ch + j;
        float dw = fmv[j] * c2w[c*3+0] + fcv[j] * c2w[c*3+1] + fpv[j] * c2w[c*3+2] + c2b[c];
        rr[j] = gelu_f(dw + fcv[j]);
    }
    int mi = (int)(row >> 7), r = (int)(row & 127);
    int ki = ch >> 6, cc = ch & 63;
    store_hl8(planeptr(outp, mi, 0, ki, 32), planeptr(outp, mi, 1, ki, 32),
              r, cc, make_float4(rr[0], rr[1], rr[2], rr[3]));
}

// ---------------- launch ------------------------------------------------------
extern "C" void kernel_launch(void* const* d_in, const int* in_sizes, int n_in,
                              void* d_out, int out_size)
{
    const float* x      = (const float*)d_in[0];
    const float* ln1_g  = (const float*)d_in[1];
    const float* ln1_b  = (const float*)d_in[2];
    const float* w_q    = (const float*)d_in[3];
    const float* w_k    = (const float*)d_in[4];
    const float* w_v    = (const float*)d_in[5];
    const float* w_o    = (const float*)d_in[6];
    const float* rel    = (const float*)d_in[7];
    const float* ln2_g  = (const float*)d_in[8];
    const float* ln2_b  = (const float*)d_in[9];
    const float* c1_w   = (const float*)d_in[10];
    const float* c1_b   = (const float*)d_in[11];
    const float* c2_w   = (const float*)d_in[12];
    const float* c2_b   = (const float*)d_in[13];
    const float* c3_w   = (const float*)d_in[14];
    const float* c3_b   = (const float*)d_in[15];
    float* out = (float*)d_out;

    __nv_bfloat16 *hp, *ctxp, *f2p, *wqkvp, *wop, *c1wp, *c3wp;
    float *q, *k, *v, *f;
    cudaGetSymbolAddress((void**)&hp,    g_hp);
    cudaGetSymbolAddress((void**)&ctxp,  g_ctxp);
    cudaGetSymbolAddress((void**)&f2p,   g_f2p);
    cudaGetSymbolAddress((void**)&wqkvp, g_wqkvp);
    cudaGetSymbolAddress((void**)&wop,   g_wop);
    cudaGetSymbolAddress((void**)&c1wp,  g_c1wp);
    cudaGetSymbolAddress((void**)&c3wp,  g_c3wp);
    cudaGetSymbolAddress((void**)&q, g_q);
    cudaGetSymbolAddress((void**)&k, g_k);
    cudaGetSymbolAddress((void**)&v, g_v);
    cudaGetSymbolAddress((void**)&f, g_f);
    float* y1 = q;

    const int write_attn = ((size_t)out_size >= Y_ELEMS + ATTN_ELEMS) ? 1 : 0;
    float* attn_out = out + Y_ELEMS;

    int nsm = 148;
    cudaDeviceGetAttribute(&nsm, cudaDevAttrMultiProcessorCount, 0);

    const int dyn = 2 * SBYTES + 1024;
    cudaFuncSetAttribute(tc_gemm<0>, cudaFuncAttributeMaxDynamicSharedMemorySize, dyn);
    cudaFuncSetAttribute(tc_gemm<1>, cudaFuncAttributeMaxDynamicSharedMemorySize, dyn);
    cudaFuncSetAttribute(tc_gemm<2>, cudaFuncAttributeMaxDynamicSharedMemorySize, dyn);
    cudaFuncSetAttribute(tc_gemm<3>, cudaFuncAttributeMaxDynamicSharedMemorySize, dyn);
    cudaFuncSetAttribute(attn_kernel, cudaFuncAttributeMaxDynamicSharedMemorySize, ATT_SMEM);

    // Keep tc_gemm<0> at MY launch idx 3 (== ncu -s 5 capture with the 2
    // harness-prepended launches).
    prep_qkv<<<dim3(12, 8), 256>>>(w_q, w_k, w_v, wqkvp);     // my 0
    ln_kernel<<<TOK, 128>>>(x, hp, ln1_g, ln1_b, 1);          // my 1
    prep_weights<<<dim3(4, 8), 256>>>(w_o, wop, CC, 0);       // my 2

    tc_gemm<0><<<nsm, 288, dyn>>>(hp, wqkvp, q, k, v,
                                  nullptr, nullptr, 8, 1536, 6, 6 * (TOK/128)); // my 3

    attn_kernel<<<dim3(NH, BB*NW), 256, ATT_SMEM>>>(q, k, v, rel, attn_out, ctxp, write_attn);

    tc_gemm<1><<<nsm, 288, dyn>>>(ctxp, wop, y1, nullptr, nullptr,
                                  nullptr, x, 8, CC, 2, 2 * (TOK/128));

    ln_kernel<<<TOK, 128>>>(y1, hp, ln2_g, ln2_b, 0);

    prep_weights<<<dim3(16, 8), 256>>>(c1_w, c1wp, CC, 0);
    tc_gemm<2><<<nsm, 288, dyn>>>(hp, c1wp, f, nullptr, nullptr,
                                  c1_b, nullptr, 8, HID, 8, 8 * (TOK/128));

    size_t nthread = (size_t)TOK * HID / 4;
    dwconv_kernel<<<(unsigned)((nthread + 255) / 256), 256>>>(f, c2_w, c2_b, f2p);

    prep_weights<<<dim3(4, 32), 256>>>(c3_w, c3wp, HID, 0);
    tc_gemm<3><<<nsm, 288, dyn>>>(f2p, c3wp, out, nullptr, nullptr,
                                  c3_b, y1, 32, CC, 2, 2 * (TOK/128));
}

// round 13
// speedup vs baseline: 1.0297x; 1.0086x over previous
#include <cuda_runtime.h>
#include <cuda_bf16.h>
#include <math.h>
#include <stdint.h>

#define BB   32
#define LL   4096
#define CC   512
#define WSZ  64
#define SHIFT 32
#define NH   8
#define DK   64
#define HID  2048
#define NW   64
#define TOK  (BB*LL)
#define Y_ELEMS   ((size_t)TOK*CC)
#define ATTN_ELEMS ((size_t)BB*NW*NH*WSZ*WSZ)
#define PLANE 8192              // elements per 128x64 bf16 plane (16KB)

// ---------------- scratch ----------------------------------------------------
// packed layout: group g, k-plane ki, split s(0=hi,1=lo):
//   offset = ((g*KT + ki)*2 + s) * PLANE       (hi/lo adjacent -> 32KB TMA)
__device__ __nv_bfloat16 g_hp   [(size_t)TOK*2*CC];
__device__ __nv_bfloat16 g_ctxp [(size_t)TOK*2*CC];
__device__ __nv_bfloat16 g_f2p  [(size_t)TOK*2*HID];
__device__ __nv_bfloat16 g_wqkvp[(size_t)(3*CC)*2*CC];
__device__ __nv_bfloat16 g_wop  [(size_t)CC*2*CC];
__device__ __nv_bfloat16 g_c1wp [(size_t)HID*2*CC];
__device__ __nv_bfloat16 g_c3wp [(size_t)CC*2*HID];
__device__ float g_q[(size_t)TOK*CC];   // q; reused as y1
__device__ float g_k[(size_t)TOK*CC];
__device__ float g_v[(size_t)TOK*CC];
__device__ float g_f[(size_t)TOK*HID];  // c1 out fp32

__device__ __forceinline__ float gelu_f(float x) {
    return 0.5f * x * (1.0f + erff(x * 0.70710678118654752440f));
}
__device__ __forceinline__ uint32_t pack_bf2(__nv_bfloat16 a, __nv_bfloat16 b) {
    return (uint32_t)__bfloat16_as_ushort(a) | ((uint32_t)__bfloat16_as_ushort(b) << 16);
}
__device__ __forceinline__ void store_hl8(
    __nv_bfloat16* hi, __nv_bfloat16* lo, int r, int cc, float4 v)
{
    int off = r * 128 + cc * 2;
    int sw  = off ^ ((off >> 3) & 0x70);
    __nv_bfloat16 h0 = __float2bfloat16(v.x), h1 = __float2bfloat16(v.y);
    __nv_bfloat16 h2 = __float2bfloat16(v.z), h3 = __float2bfloat16(v.w);
    __nv_bfloat16 l0 = __float2bfloat16(v.x - __bfloat162float(h0));
    __nv_bfloat16 l1 = __float2bfloat16(v.y - __bfloat162float(h1));
    __nv_bfloat16 l2 = __float2bfloat16(v.z - __bfloat162float(h2));
    __nv_bfloat16 l3 = __float2bfloat16(v.w - __bfloat162float(h3));
    *(uint2*)((char*)hi + sw) = make_uint2(pack_bf2(h0, h1), pack_bf2(h2, h3));
    *(uint2*)((char*)lo + sw) = make_uint2(pack_bf2(l0, l1), pack_bf2(l2, l3));
}
__device__ __forceinline__ __nv_bfloat16* planeptr(
    __nv_bfloat16* buf, int g, int s, int ki, int KT)
{
    return buf + (((size_t)g * KT + ki) * 2 + s) * PLANE;
}

// ---------------- weight prep -------------------------------------------------
__global__ void __launch_bounds__(256) prep_weights(
    const float* __restrict__ W, __nv_bfloat16* __restrict__ Wp,
    int K, int groupOffset)
{
    const int g = blockIdx.x, ki = blockIdx.y;
    const int KT = K >> 6;
    const int t = threadIdx.x;
    const int r = t >> 1, c0 = (t & 1) * 32;
    __nv_bfloat16* hi = planeptr(Wp, groupOffset + g, 0, ki, KT);
    __nv_bfloat16* lo = planeptr(Wp, groupOffset + g, 1, ki, KT);
    const float* src = W + (size_t)(g * 128 + r) * K + ki * 64;
    #pragma unroll
    for (int i = 0; i < 8; i++) {
        int c = c0 + i * 4;
        store_hl8(hi, lo, r, c, *(const float4*)(src + c));
    }
}

// fused qkv weight prep: groups 0-3 <- w_q, 4-7 <- w_k, 8-11 <- w_v (K=512)
__global__ void __launch_bounds__(256) prep_qkv(
    const float* __restrict__ Wq, const float* __restrict__ Wk,
    const float* __restrict__ Wv, __nv_bfloat16* __restrict__ Wp)
{
    const int g = blockIdx.x, ki = blockIdx.y;     // g 0..11, ki 0..7
    const int t = threadIdx.x;
    const int r = t >> 1, c0 = (t & 1) * 32;
    const float* W = (g < 4) ? Wq : (g < 8) ? Wk : Wv;
    const int gl = g & 3;
    __nv_bfloat16* hi = planeptr(Wp, g, 0, ki, 8);
    __nv_bfloat16* lo = planeptr(Wp, g, 1, ki, 8);
    const float* src = W + (size_t)(gl * 128 + r) * CC + ki * 64;
    #pragma unroll
    for (int i = 0; i < 8; i++) {
        int c = c0 + i * 4;
        store_hl8(hi, lo, r, c, *(const float4*)(src + c));
    }
}

// ---------------- LayerNorm (+roll) -> packed planes (KT=8) -------------------
__global__ void __launch_bounds__(128) ln_kernel(
    const float* __restrict__ x, __nv_bfloat16* __restrict__ outp,
    const float* __restrict__ g, const float* __restrict__ b, int rolled)
{
    int row = blockIdx.x;
    int bt  = row >> 12, l = row & (LL - 1);
    int src = rolled ? ((bt << 12) | ((l + SHIFT) & (LL - 1))) : row;
    const float* xr = x + (size_t)src * CC;

    int t = threadIdx.x;
    float4 v = *(const float4*)(xr + t * 4);
    float s  = v.x + v.y + v.z + v.w;
    float ss = v.x*v.x + v.y*v.y + v.z*v.z + v.w*v.w;
    #pragma unroll
    for (int o = 16; o > 0; o >>= 1) {
        s  += __shfl_xor_sync(0xffffffffu, s,  o);
        ss += __shfl_xor_sync(0xffffffffu, ss, o);
    }
    __shared__ float red[8];
    int wid = t >> 5, lid = t & 31;
    if (lid == 0) { red[wid] = s; red[4 + wid] = ss; }
    __syncthreads();
    s  = red[0] + red[1] + red[2] + red[3];
    ss = red[4] + red[5] + red[6] + red[7];
    float mean = s * (1.0f / CC);
    float rstd = rsqrtf(ss * (1.0f / CC) - mean * mean + 1e-5f);

    float4 gg = *(const float4*)(g + t * 4);
    float4 bb = *(const float4*)(b + t * 4);
    float4 o4;
    o4.x = (v.x - mean) * rstd * gg.x + bb.x;
    o4.y = (v.y - mean) * rstd * gg.y + bb.y;
    o4.z = (v.z - mean) * rstd * gg.z + bb.z;
    o4.w = (v.w - mean) * rstd * gg.w + bb.w;

    int mi = row >> 7, r = row & 127;
    int ki = t >> 4, cc = (4 * t) & 63;
    store_hl8(planeptr(outp, mi, 0, ki, 8), planeptr(outp, mi, 1, ki, 8), r, cc, o4);
}

// ---------------- async-feed bf16x3 mma.sync GEMM (persistent CTAs) ----------
__device__ __forceinline__ uint32_t cvta_smem(const void* p) {
    return (uint32_t)__cvta_generic_to_shared(p);
}
__device__ __forceinline__ void ldsm4(uint32_t* r, uint32_t addr) {
    asm volatile("ldmatrix.sync.aligned.m8n8.x4.shared.b16 {%0,%1,%2,%3}, [%4];"
        : "=r"(r[0]), "=r"(r[1]), "=r"(r[2]), "=r"(r[3]) : "r"(addr));
}
__device__ __forceinline__ void mma16816(float* c, const uint32_t* a, const uint32_t* b) {
    asm volatile("mma.sync.aligned.m16n8k16.row.col.f32.bf16.bf16.f32 "
        "{%0,%1,%2,%3},{%4,%5,%6,%7},{%8,%9},{%0,%1,%2,%3};"
        : "+f"(c[0]), "+f"(c[1]), "+f"(c[2]), "+f"(c[3])
        : "r"(a[0]), "r"(a[1]), "r"(a[2]), "r"(a[3]), "r"(b[0]), "r"(b[1]));
}
__device__ __forceinline__ void mbar_init(uint32_t a, uint32_t c) {
    asm volatile("mbarrier.init.shared.b64 [%0], %1;" :: "r"(a), "r"(c) : "memory");
}
__device__ __forceinline__ void mbar_expect_tx(uint32_t a, uint32_t bytes) {
    asm volatile("mbarrier.arrive.expect_tx.shared.b64 _, [%0], %1;"
                 :: "r"(a), "r"(bytes) : "memory");
}
__device__ __forceinline__ void mbar_arrive(uint32_t a) {
    asm volatile("mbarrier.arrive.shared.b64 _, [%0];" :: "r"(a) : "memory");
}
__device__ __forceinline__ void mbar_wait(uint32_t a, uint32_t p) {
    asm volatile(
        "{\n\t.reg .pred P;\n\tLW%=:\n\t"
        "mbarrier.try_wait.parity.acquire.cta.shared::cta.b64 P, [%0], %1;\n\t"
        "@!P bra LW%=;\n\t}" :: "r"(a), "r"(p) : "memory");
}
__device__ __forceinline__ void bulk_cp(uint32_t dst, const void* src,
                                        uint32_t bytes, uint32_t mbar) {
    asm volatile(
        "cp.async.bulk.shared::cluster.global.mbarrier::complete_tx::bytes "
        "[%0], [%1], %2, [%3];"
        :: "r"(dst), "l"(src), "r"(bytes), "r"(mbar) : "memory");
}
__device__ __forceinline__ uint32_t segaddr(uint32_t base, int r, int kc) {
    return base + r * 128 + ((((kc >> 3) ^ (r & 7)) & 7) << 4);
}

#define SBYTES 98304u   // Ah|Al | B0h|B0l | B1h|B1l

// MODE 0: qkv split  1: roll+residual  2: +bias GELU  3: +bias+addsrc
// Persistent: grid = numSM; each CTA strides over (mi, ni) tiles; the 2-deep
// TMA ring runs on a GLOBAL stage counter so prologue/epilogue of successive
// tiles overlap with the async feed. Consumer kf-loop batches ALL 12 ldsm
// first (pass-order), then runs 96 MMAs: first-pass operands are the oldest
// loads, later passes' operands land under the MMA shadow.
template<int MODE>
__global__ void __launch_bounds__(288) tc_gemm(
    const __nv_bfloat16* __restrict__ Ap, const __nv_bfloat16* __restrict__ Bp,
    float* __restrict__ O0, float* __restrict__ O1, float* __restrict__ O2,
    const float* __restrict__ bias, const float* __restrict__ addsrc,
    int KT, int Ntot, int NTX, int ntiles)
{
    extern __shared__ char dsm[];
    __shared__ __align__(8) uint64_t s_mbar[4];   // full0 full1 empty0 empty1

    const uint32_t sb  = (cvta_smem(dsm) + 1023u) & ~1023u;
    const uint32_t mbF = cvta_smem(&s_mbar[0]);
    const uint32_t mbE = cvta_smem(&s_mbar[2]);
    const int tid = threadIdx.x;
    const int wid = tid >> 5, lane = tid & 31;

    if (tid == 0) {
        mbar_init(mbF, 1); mbar_init(mbF + 8, 1);
        mbar_init(mbE, 8); mbar_init(mbE + 8, 8);
        asm volatile("fence.proxy.async.shared::cta;" ::: "memory");
    }
    __syncthreads();

    if (wid == 8) {
        // ---- producer warp: continuous ring across all tiles ----
        if (lane == 0) {
            int gs = 0;
            for (int tile = blockIdx.x; tile < ntiles; tile += gridDim.x) {
                const int ni = tile % NTX, mi = tile / NTX;
                for (int s = 0; s < KT; s++, gs++) {
                    if (gs >= 2) mbar_wait(mbE + (gs & 1) * 8, (uint32_t)(((gs - 2) >> 1) & 1));
                    int b = gs & 1;
                    uint32_t d = sb + b * SBYTES;
                    uint32_t m = mbF + b * 8;
                    mbar_expect_tx(m, SBYTES);
                    bulk_cp(d,         Ap + (((size_t)mi       * KT + s) * 2) * PLANE, 32768, m);
                    bulk_cp(d + 32768, Bp + (((size_t)(2*ni)   * KT + s) * 2) * PLANE, 32768, m);
                    bulk_cp(d + 65536, Bp + (((size_t)(2*ni+1) * KT + s) * 2) * PLANE, 32768, m);
                }
            }
        }
        return;
    }

    // ---- consumer warps (0-7) ----
    const int wm = (wid & 1) * 64;
    const int wn = (wid >> 1) * 64;
    const int bplane = (wn >> 7);
    const int wnl = wn & 127;
    const int arow0 = wm + (lane & 15);
    const int akc0  = (lane >> 4) * 8;
    const int brow0 = wnl + ((lane >> 4) & 1) * 8 + (lane & 7);
    const int bkc0  = ((lane >> 3) & 1) * 8;
    const int rb0 = wm + (lane >> 2);
    const int cb  = wn + (lane & 3) * 2;

    int gs = 0;
    for (int tile = blockIdx.x; tile < ntiles; tile += gridDim.x) {
        const int ni = tile % NTX, mi = tile / NTX;

        float acc[4][8][4];
        #pragma unroll
        for (int a = 0; a < 4; a++)
            #pragma unroll
            for (int b = 0; b < 8; b++)
                #pragma unroll
                for (int c = 0; c < 4; c++) acc[a][b][c] = 0.0f;

        for (int s = 0; s < KT; s++, gs++) {
            int b = gs & 1;
            mbar_wait(mbF + b * 8, (uint32_t)((gs >> 1) & 1));
            const uint32_t Ah = sb + b * SBYTES;
            const uint32_t Al = Ah + 16384;
            const uint32_t Bh = Ah + 32768 + bplane * 32768;
            const uint32_t Bl = Bh + 16384;

            #pragma unroll
            for (int kf = 0; kf < 4; kf++) {
                const int k0 = kf * 16;
                const int akc = k0 + akc0;
                const int bkc = k0 + bkc0;
                uint32_t fa[4][4], fal[4][4], fbh[4][4], fbl[4][4];

                // ---- issue ALL fragment loads up front, in pass order ----
                #pragma unroll
                for (int mt = 0; mt < 4; mt++)
                    ldsm4(fa[mt], segaddr(Ah, arow0 + mt * 16, akc));
                #pragma unroll
                for (int j = 0; j < 4; j++)
                    ldsm4(fbh[j], segaddr(Bh, brow0 + j * 16, bkc));
                #pragma unroll
                for (int mt = 0; mt < 4; mt++)
                    ldsm4(fal[mt], segaddr(Al, arow0 + mt * 16, akc));
                #pragma unroll
                for (int j = 0; j < 4; j++)
                    ldsm4(fbl[j], segaddr(Bl, brow0 + j * 16, bkc));
                // stage fully read once these loads retire; release early so
                // the producer can start the next TMA under pass 1-3.
                if (kf == 3 && lane == 0) mbar_arrive(mbE + b * 8);

                // ---- pass 1: Ah * Bh ----
                #pragma unroll
                for (int mt = 0; mt < 4; mt++)
                    #pragma unroll
                    for (int j = 0; j < 4; j++) {
                        mma16816(acc[mt][2*j],   fa[mt], &fbh[j][0]);
                        mma16816(acc[mt][2*j+1], fa[mt], &fbh[j][2]);
                    }
                // ---- pass 2: Al * Bh ----
                #pragma unroll
                for (int mt = 0; mt < 4; mt++)
                    #pragma unroll
                    for (int j = 0; j < 4; j++) {
                        mma16816(acc[mt][2*j],   fal[mt], &fbh[j][0]);
                        mma16816(acc[mt][2*j+1], fal[mt], &fbh[j][2]);
                    }
                // ---- pass 3: Ah * Bl ----
                #pragma unroll
                for (int mt = 0; mt < 4; mt++)
                    #pragma unroll
                    for (int j = 0; j < 4; j++) {
                        mma16816(acc[mt][2*j],   fa[mt], &fbl[j][0]);
                        mma16816(acc[mt][2*j+1], fa[mt], &fbl[j][2]);
                    }
            }
        }

        // epilogue for this tile (producer already prefetching next tile)
        const int rb = mi * 128 + rb0;
        #pragma unroll
        for (int mt = 0; mt < 4; mt++) {
            #pragma unroll
            for (int half = 0; half < 2; half++) {
                const int m = rb + mt * 16 + half * 8;
                #pragma unroll
                for (int nt = 0; nt < 8; nt++) {
                    const int n = ni * 256 + cb + nt * 8;
                    float v0 = acc[mt][nt][half * 2 + 0];
                    float v1 = acc[mt][nt][half * 2 + 1];
                    if (MODE == 0) {
                        int buf = n >> 9, col = n & 511;
                        float* dst = (buf == 0 ? O0 : (buf == 1 ? O1 : O2));
                        *(float2*)(dst + (size_t)m * CC + col) = make_float2(v0, v1);
                    } else if (MODE == 1) {
                        int bt = m >> 12, l = m & (LL - 1);
                        size_t mrow = ((size_t)(bt << 12) | ((l + SHIFT) & (LL - 1)));
                        float2 r0 = *(const float2*)(addsrc + mrow * Ntot + n);
                        *(float2*)(O0 + mrow * Ntot + n) = make_float2(v0 + r0.x, v1 + r0.y);
                    } else if (MODE == 2) {
                        float2 b2 = *(const float2*)(bias + n);
                        *(float2*)(O0 + (size_t)m * Ntot + n) =
                            make_float2(gelu_f(v0 + b2.x), gelu_f(v1 + b2.y));
                    } else {
                        float2 b2 = *(const float2*)(bias + n);
                        float2 r0 = *(const float2*)(addsrc + (size_t)m * Ntot + n);
                        *(float2*)(O0 + (size_t)m * Ntot + n) =
                            make_float2(v0 + b2.x + r0.x, v1 + b2.y + r0.y);
                    }
                }
            }
        }
    }
}

// ---------------- window attention: 4x4 microtile version ---------------------
#define ATT_SQ   0
#define ATT_SK   (64*68)
#define ATT_SV   (ATT_SK + 64*64)
#define ATT_SB   (ATT_SV + 64*64)
#define ATT_SMEM ((ATT_SB + 128) * 4)

__global__ void __launch_bounds__(256) attn_kernel(
    const float* __restrict__ q, const float* __restrict__ k, const float* __restrict__ v,
    const float* __restrict__ rel_table,
    float* __restrict__ attn_out, __nv_bfloat16* __restrict__ ctxp, int write_attn)
{
    extern __shared__ float smf[];
    float* sQ = smf + ATT_SQ;
    float* sK = smf + ATT_SK;
    float* sV = smf + ATT_SV;
    float* sB = smf + ATT_SB;

    const int h = blockIdx.x;
    const int w = blockIdx.y;
    const int tid = threadIdx.x;
    const size_t base = (size_t)w * WSZ * CC + (size_t)h * DK;

    {
        int t = tid >> 2, qd = tid & 3;
        #pragma unroll
        for (int i = 0; i < 4; i++) {
            int d0 = qd * 16 + i * 4;
            float4 qv = *(const float4*)(q + base + (size_t)t * CC + d0);
            sQ[(d0+0)*68 + t] = qv.x; sQ[(d0+1)*68 + t] = qv.y;
            sQ[(d0+2)*68 + t] = qv.z; sQ[(d0+3)*68 + t] = qv.w;
            float4 kv = *(const float4*)(k + base + (size_t)t * CC + d0);
            sK[(d0+0)*64 + t] = kv.x; sK[(d0+1)*64 + t] = kv.y;
            sK[(d0+2)*64 + t] = kv.z; sK[(d0+3)*64 + t] = kv.w;
            float4 vv = *(const float4*)(v + base + (size_t)t * CC + d0);
            *(float4*)(sV + t * 64 + d0) = vv;
        }
        if (tid < 127) sB[tid] = rel_table[tid * NH + h];
    }
    __syncthreads();

    const int ty = tid >> 4, tx = tid & 15;
    float sc[4][4];
    #pragma unroll
    for (int i = 0; i < 4; i++)
        #pragma unroll
        for (int j = 0; j < 4; j++) sc[i][j] = 0.0f;

    #pragma unroll 8
    for (int d = 0; d < 64; d++) {
        float4 qv = *(const float4*)(sQ + d * 68 + ty * 4);
        float4 kv = *(const float4*)(sK + d * 64 + tx * 4);
        float qa[4] = {qv.x, qv.y, qv.z, qv.w};
        float ka[4] = {kv.x, kv.y, kv.z, kv.w};
        #pragma unroll
        for (int i = 0; i < 4; i++)
            #pragma unroll
            for (int j = 0; j < 4; j++)
                sc[i][j] += qa[i] * ka[j];
    }

    const bool last = ((w & (NW - 1)) == (NW - 1));
    #pragma unroll
    for (int i = 0; i < 4; i++) {
        int t = ty * 4 + i;
        #pragma unroll
        for (int j = 0; j < 4; j++) {
            int t2 = tx * 4 + j;
            float s = sc[i][j] * 0.125f + sB[t - t2 + 63];
            if (last && ((t < 32) != (t2 < 32))) s -= 100.0f;
            sc[i][j] = s;
        }
    }

    #pragma unroll
    for (int i = 0; i < 4; i++) {
        float m = fmaxf(fmaxf(sc[i][0], sc[i][1]), fmaxf(sc[i][2], sc[i][3]));
        m = fmaxf(m, __shfl_xor_sync(0xffffffffu, m, 1));
        m = fmaxf(m, __shfl_xor_sync(0xffffffffu, m, 2));
        m = fmaxf(m, __shfl_xor_sync(0xffffffffu, m, 4));
        m = fmaxf(m, __shfl_xor_sync(0xffffffffu, m, 8));
        float s = 0.0f;
        #pragma unroll
        for (int j = 0; j < 4; j++) { sc[i][j] = __expf(sc[i][j] - m); s += sc[i][j]; }
        s += __shfl_xor_sync(0xffffffffu, s, 1);
        s += __shfl_xor_sync(0xffffffffu, s, 2);
        s += __shfl_xor_sync(0xffffffffu, s, 4);
        s += __shfl_xor_sync(0xffffffffu, s, 8);
        float inv = 1.0f / s;
        #pragma unroll
        for (int j = 0; j < 4; j++) sc[i][j] *= inv;
    }

    if (write_attn) {
        #pragma unroll
        for (int i = 0; i < 4; i++) {
            int t = ty * 4 + i;
            size_t ao = ((((size_t)w * NH + h) * WSZ) + t) * WSZ + tx * 4;
            *(float4*)(attn_out + ao) = make_float4(sc[i][0], sc[i][1], sc[i][2], sc[i][3]);
        }
    }

    __syncthreads();
    #pragma unroll
    for (int i = 0; i < 4; i++) {
        int t = ty * 4 + i;
        #pragma unroll
        for (int j = 0; j < 4; j++)
            sQ[(tx * 4 + j) * 68 + t] = sc[i][j];
    }
    __syncthreads();

    float oa[4][4];
    #pragma unroll
    for (int i = 0; i < 4; i++)
        #pragma unroll
        for (int j = 0; j < 4; j++) oa[i][j] = 0.0f;

    #pragma unroll 8
    for (int t2 = 0; t2 < 64; t2++) {
        float4 sv = *(const float4*)(sQ + t2 * 68 + ty * 4);
        float4 vv = *(const float4*)(sV + t2 * 64 + tx * 4);
        float sa[4] = {sv.x, sv.y, sv.z, sv.w};
        float va[4] = {vv.x, vv.y, vv.z, vv.w};
        #pragma unroll
        for (int i = 0; i < 4; i++)
            #pragma unroll
            for (int j = 0; j < 4; j++)
                oa[i][j] += sa[i] * va[j];
    }

    #pragma unroll
    for (int i = 0; i < 4; i++) {
        int gr = w * WSZ + ty * 4 + i;
        int mi = gr >> 7, r = gr & 127;
        store_hl8(planeptr(ctxp, mi, 0, h, 8), planeptr(ctxp, mi, 1, h, 8),
                  r, tx * 4, make_float4(oa[i][0], oa[i][1], oa[i][2], oa[i][3]));
    }
}

// ---------------- dwconv (k=3) + GELU -> packed planes (KT=32) ----------------
__global__ void __launch_bounds__(256) dwconv_kernel(
    const float* __restrict__ f, const float* __restrict__ c2w,
    const float* __restrict__ c2b, __nv_bfloat16* __restrict__ outp)
{
    size_t idx = (size_t)blockIdx.x * blockDim.x + threadIdx.x;
    if (idx >= (size_t)TOK * HID / 4) return;
    size_t e = idx * 4;
    int ch = (int)(e % HID);
    size_t row = e / HID;
    int l = (int)(row & (LL - 1));

    float4 fc = *(const float4*)(f + e);
    float4 fm = make_float4(0.f, 0.f, 0.f, 0.f);
    float4 fp = make_float4(0.f, 0.f, 0.f, 0.f);
    if (l > 0)      fm = *(const float4*)(f + e - HID);
    if (l < LL - 1) fp = *(const float4*)(f + e + HID);

    float rr[4];
    float fmv[4] = {fm.x, fm.y, fm.z, fm.w};
    float fcv[4] = {fc.x, fc.y, fc.z, fc.w};
    float fpv[4] = {fp.x, fp.y, fp.z, fp.w};
    #pragma unroll
    for (int j = 0; j < 4; j++) {
        int c = ch + j;
        float dw = fmv[j] * c2w[c*3+0] + fcv[j] * c2w[c*3+1] + fpv[j] * c2w[c*3+2] + c2b[c];
        rr[j] = gelu_f(dw + fcv[j]);
    }
    int mi = (int)(row >> 7), r = (int)(row & 127);
    int ki = ch >> 6, cc = ch & 63;
    store_hl8(planeptr(outp, mi, 0, ki, 32), planeptr(outp, mi, 1, ki, 32),
              r, cc, make_float4(rr[0], rr[1], rr[2], rr[3]));
}

// ---------------- launch ------------------------------------------------------
extern "C" void kernel_launch(void* const* d_in, const int* in_sizes, int n_in,
                              void* d_out, int out_size)
{
    const float* x      = (const float*)d_in[0];
    const float* ln1_g  = (const float*)d_in[1];
    const float* ln1_b  = (const float*)d_in[2];
    const float* w_q    = (const float*)d_in[3];
    const float* w_k    = (const float*)d_in[4];
    const float* w_v    = (const float*)d_in[5];
    const float* w_o    = (const float*)d_in[6];
    const float* rel    = (const float*)d_in[7];
    const float* ln2_g  = (const float*)d_in[8];
    const float* ln2_b  = (const float*)d_in[9];
    const float* c1_w   = (const float*)d_in[10];
    const float* c1_b   = (const float*)d_in[11];
    const float* c2_w   = (const float*)d_in[12];
    const float* c2_b   = (const float*)d_in[13];
    const float* c3_w   = (const float*)d_in[14];
    const float* c3_b   = (const float*)d_in[15];
    float* out = (float*)d_out;

    __nv_bfloat16 *hp, *ctxp, *f2p, *wqkvp, *wop, *c1wp, *c3wp;
    float *q, *k, *v, *f;
    cudaGetSymbolAddress((void**)&hp,    g_hp);
    cudaGetSymbolAddress((void**)&ctxp,  g_ctxp);
    cudaGetSymbolAddress((void**)&f2p,   g_f2p);
    cudaGetSymbolAddress((void**)&wqkvp, g_wqkvp);
    cudaGetSymbolAddress((void**)&wop,   g_wop);
    cudaGetSymbolAddress((void**)&c1wp,  g_c1wp);
    cudaGetSymbolAddress((void**)&c3wp,  g_c3wp);
    cudaGetSymbolAddress((void**)&q, g_q);
    cudaGetSymbolAddress((void**)&k, g_k);
    cudaGetSymbolAddress((void**)&v, g_v);
    cudaGetSymbolAddress((void**)&f, g_f);
    float* y1 = q;

    const int write_attn = ((size_t)out_size >= Y_ELEMS + ATTN_ELEMS) ? 1 : 0;
    float* attn_out = out + Y_ELEMS;

    int nsm = 148;
    cudaDeviceGetAttribute(&nsm, cudaDevAttrMultiProcessorCount, 0);

    const int dyn = 2 * SBYTES + 1024;
    cudaFuncSetAttribute(tc_gemm<0>, cudaFuncAttributeMaxDynamicSharedMemorySize, dyn);
    cudaFuncSetAttribute(tc_gemm<1>, cudaFuncAttributeMaxDynamicSharedMemorySize, dyn);
    cudaFuncSetAttribute(tc_gemm<2>, cudaFuncAttributeMaxDynamicSharedMemorySize, dyn);
    cudaFuncSetAttribute(tc_gemm<3>, cudaFuncAttributeMaxDynamicSharedMemorySize, dyn);
    cudaFuncSetAttribute(attn_kernel, cudaFuncAttributeMaxDynamicSharedMemorySize, ATT_SMEM);

    // Keep tc_gemm<0> at MY launch idx 3 (== ncu -s 5 capture with the 2
    // harness-prepended launches).
    prep_qkv<<<dim3(12, 8), 256>>>(w_q, w_k, w_v, wqkvp);     // my 0
    ln_kernel<<<TOK, 128>>>(x, hp, ln1_g, ln1_b, 1);          // my 1
    prep_weights<<<dim3(4, 8), 256>>>(w_o, wop, CC, 0);       // my 2

    tc_gemm<0><<<nsm, 288, dyn>>>(hp, wqkvp, q, k, v,
                                  nullptr, nullptr, 8, 1536, 6, 6 * (TOK/128)); // my 3

    attn_kernel<<<dim3(NH, BB*NW), 256, ATT_SMEM>>>(q, k, v, rel, attn_out, ctxp, write_attn);

    tc_gemm<1><<<nsm, 288, dyn>>>(ctxp, wop, y1, nullptr, nullptr,
                                  nullptr, x, 8, CC, 2, 2 * (TOK/128));

    ln_kernel<<<TOK, 128>>>(y1, hp, ln2_g, ln2_b, 0);

    prep_weights<<<dim3(16, 8), 256>>>(c1_w, c1wp, CC, 0);
    tc_gemm<2><<<nsm, 288, dyn>>>(hp, c1wp, f, nullptr, nullptr,
                                  c1_b, nullptr, 8, HID, 8, 8 * (TOK/128));

    size_t nthread = (size_t)TOK * HID / 4;
    dwconv_kernel<<<(unsigned)((nthread + 255) / 256), 256>>>(f, c2_w, c2_b, f2p);

    prep_weights<<<dim3(4, 32), 256>>>(c3_w, c3wp, HID, 0);
    tc_gemm<3><<<nsm, 288, dyn>>>(f2p, c3wp, out, nullptr, nullptr,
                                  c3_b, y1, 32, CC, 2, 2 * (TOK/128));
}

// round 14
// speedup vs baseline: 1.0847x; 1.0534x over previous
#include <cuda_runtime.h>
#include <cuda_bf16.h>
#include <math.h>
#include <stdint.h>

#define BB   32
#define LL   4096
#define CC   512
#define WSZ  64
#define SHIFT 32
#define NH   8
#define DK   64
#define HID  2048
#define NW   64
#define TOK  (BB*LL)
#define Y_ELEMS   ((size_t)TOK*CC)
#define ATTN_ELEMS ((size_t)BB*NW*NH*WSZ*WSZ)
#define PLANE 8192              // elements per 128x64 bf16 plane (16KB)

// ---------------- scratch ----------------------------------------------------
// packed layout: group g, k-plane ki, split s(0=hi,1=lo):
//   offset = ((g*KT + ki)*2 + s) * PLANE       (hi/lo adjacent -> 32KB TMA)
__device__ __nv_bfloat16 g_hp   [(size_t)TOK*2*CC];
__device__ __nv_bfloat16 g_ctxp [(size_t)TOK*2*CC];
__device__ __nv_bfloat16 g_f2p  [(size_t)TOK*2*HID];
__device__ __nv_bfloat16 g_wqkvp[(size_t)(3*CC)*2*CC];
__device__ __nv_bfloat16 g_wop  [(size_t)CC*2*CC];
__device__ __nv_bfloat16 g_c1wp [(size_t)HID*2*CC];
__device__ __nv_bfloat16 g_c3wp [(size_t)CC*2*HID];
__device__ float g_q[(size_t)TOK*CC];   // q; reused as y1
__device__ float g_k[(size_t)TOK*CC];
__device__ float g_v[(size_t)TOK*CC];
__device__ float g_f[(size_t)TOK*HID];  // c1 out fp32

__device__ __forceinline__ float gelu_f(float x) {
    return 0.5f * x * (1.0f + erff(x * 0.70710678118654752440f));
}
__device__ __forceinline__ uint32_t pack_bf2(__nv_bfloat16 a, __nv_bfloat16 b) {
    return (uint32_t)__bfloat16_as_ushort(a) | ((uint32_t)__bfloat16_as_ushort(b) << 16);
}
__device__ __forceinline__ void store_hl8(
    __nv_bfloat16* hi, __nv_bfloat16* lo, int r, int cc, float4 v)
{
    int off = r * 128 + cc * 2;
    int sw  = off ^ ((off >> 3) & 0x70);
    __nv_bfloat16 h0 = __float2bfloat16(v.x), h1 = __float2bfloat16(v.y);
    __nv_bfloat16 h2 = __float2bfloat16(v.z), h3 = __float2bfloat16(v.w);
    __nv_bfloat16 l0 = __float2bfloat16(v.x - __bfloat162float(h0));
    __nv_bfloat16 l1 = __float2bfloat16(v.y - __bfloat162float(h1));
    __nv_bfloat16 l2 = __float2bfloat16(v.z - __bfloat162float(h2));
    __nv_bfloat16 l3 = __float2bfloat16(v.w - __bfloat162float(h3));
    *(uint2*)((char*)hi + sw) = make_uint2(pack_bf2(h0, h1), pack_bf2(h2, h3));
    *(uint2*)((char*)lo + sw) = make_uint2(pack_bf2(l0, l1), pack_bf2(l2, l3));
}
__device__ __forceinline__ __nv_bfloat16* planeptr(
    __nv_bfloat16* buf, int g, int s, int ki, int KT)
{
    return buf + (((size_t)g * KT + ki) * 2 + s) * PLANE;
}

// ---------------- weight prep -------------------------------------------------
__global__ void __launch_bounds__(256) prep_weights(
    const float* __restrict__ W, __nv_bfloat16* __restrict__ Wp,
    int K, int groupOffset)
{
    const int g = blockIdx.x, ki = blockIdx.y;
    const int KT = K >> 6;
    const int t = threadIdx.x;
    const int r = t >> 1, c0 = (t & 1) * 32;
    __nv_bfloat16* hi = planeptr(Wp, groupOffset + g, 0, ki, KT);
    __nv_bfloat16* lo = planeptr(Wp, groupOffset + g, 1, ki, KT);
    const float* src = W + (size_t)(g * 128 + r) * K + ki * 64;
    #pragma unroll
    for (int i = 0; i < 8; i++) {
        int c = c0 + i * 4;
        store_hl8(hi, lo, r, c, *(const float4*)(src + c));
    }
}

// fused qkv weight prep: groups 0-3 <- w_q, 4-7 <- w_k, 8-11 <- w_v (K=512)
__global__ void __launch_bounds__(256) prep_qkv(
    const float* __restrict__ Wq, const float* __restrict__ Wk,
    const float* __restrict__ Wv, __nv_bfloat16* __restrict__ Wp)
{
    const int g = blockIdx.x, ki = blockIdx.y;     // g 0..11, ki 0..7
    const int t = threadIdx.x;
    const int r = t >> 1, c0 = (t & 1) * 32;
    const float* W = (g < 4) ? Wq : (g < 8) ? Wk : Wv;
    const int gl = g & 3;
    __nv_bfloat16* hi = planeptr(Wp, g, 0, ki, 8);
    __nv_bfloat16* lo = planeptr(Wp, g, 1, ki, 8);
    const float* src = W + (size_t)(gl * 128 + r) * CC + ki * 64;
    #pragma unroll
    for (int i = 0; i < 8; i++) {
        int c = c0 + i * 4;
        store_hl8(hi, lo, r, c, *(const float4*)(src + c));
    }
}

// ---------------- LayerNorm (+roll) -> packed planes (KT=8) -------------------
__global__ void __launch_bounds__(128) ln_kernel(
    const float* __restrict__ x, __nv_bfloat16* __restrict__ outp,
    const float* __restrict__ g, const float* __restrict__ b, int rolled)
{
    int row = blockIdx.x;
    int bt  = row >> 12, l = row & (LL - 1);
    int src = rolled ? ((bt << 12) | ((l + SHIFT) & (LL - 1))) : row;
    const float* xr = x + (size_t)src * CC;

    int t = threadIdx.x;
    float4 v = *(const float4*)(xr + t * 4);
    float s  = v.x + v.y + v.z + v.w;
    float ss = v.x*v.x + v.y*v.y + v.z*v.z + v.w*v.w;
    #pragma unroll
    for (int o = 16; o > 0; o >>= 1) {
        s  += __shfl_xor_sync(0xffffffffu, s,  o);
        ss += __shfl_xor_sync(0xffffffffu, ss, o);
    }
    __shared__ float red[8];
    int wid = t >> 5, lid = t & 31;
    if (lid == 0) { red[wid] = s; red[4 + wid] = ss; }
    __syncthreads();
    s  = red[0] + red[1] + red[2] + red[3];
    ss = red[4] + red[5] + red[6] + red[7];
    float mean = s * (1.0f / CC);
    float rstd = rsqrtf(ss * (1.0f / CC) - mean * mean + 1e-5f);

    float4 gg = *(const float4*)(g + t * 4);
    float4 bb = *(const float4*)(b + t * 4);
    float4 o4;
    o4.x = (v.x - mean) * rstd * gg.x + bb.x;
    o4.y = (v.y - mean) * rstd * gg.y + bb.y;
    o4.z = (v.z - mean) * rstd * gg.z + bb.z;
    o4.w = (v.w - mean) * rstd * gg.w + bb.w;

    int mi = row >> 7, r = row & 127;
    int ki = t >> 4, cc = (4 * t) & 63;
    store_hl8(planeptr(outp, mi, 0, ki, 8), planeptr(outp, mi, 1, ki, 8), r, cc, o4);
}

// ---------------- async-feed bf16x3 mma.sync GEMM (persistent CTAs) ----------
__device__ __forceinline__ uint32_t cvta_smem(const void* p) {
    return (uint32_t)__cvta_generic_to_shared(p);
}
__device__ __forceinline__ void ldsm4(uint32_t* r, uint32_t addr) {
    asm volatile("ldmatrix.sync.aligned.m8n8.x4.shared.b16 {%0,%1,%2,%3}, [%4];"
        : "=r"(r[0]), "=r"(r[1]), "=r"(r[2]), "=r"(r[3]) : "r"(addr));
}
__device__ __forceinline__ void mma16816(float* c, const uint32_t* a, const uint32_t* b) {
    asm volatile("mma.sync.aligned.m16n8k16.row.col.f32.bf16.bf16.f32 "
        "{%0,%1,%2,%3},{%4,%5,%6,%7},{%8,%9},{%0,%1,%2,%3};"
        : "+f"(c[0]), "+f"(c[1]), "+f"(c[2]), "+f"(c[3])
        : "r"(a[0]), "r"(a[1]), "r"(a[2]), "r"(a[3]), "r"(b[0]), "r"(b[1]));
}
__device__ __forceinline__ void mbar_init(uint32_t a, uint32_t c) {
    asm volatile("mbarrier.init.shared.b64 [%0], %1;" :: "r"(a), "r"(c) : "memory");
}
__device__ __forceinline__ void mbar_expect_tx(uint32_t a, uint32_t bytes) {
    asm volatile("mbarrier.arrive.expect_tx.shared.b64 _, [%0], %1;"
                 :: "r"(a), "r"(bytes) : "memory");
}
__device__ __forceinline__ void mbar_arrive(uint32_t a) {
    asm volatile("mbarrier.arrive.shared.b64 _, [%0];" :: "r"(a) : "memory");
}
__device__ __forceinline__ void mbar_wait(uint32_t a, uint32_t p) {
    asm volatile(
        "{\n\t.reg .pred P;\n\tLW%=:\n\t"
        "mbarrier.try_wait.parity.acquire.cta.shared::cta.b64 P, [%0], %1;\n\t"
        "@!P bra LW%=;\n\t}" :: "r"(a), "r"(p) : "memory");
}
__device__ __forceinline__ void bulk_cp(uint32_t dst, const void* src,
                                        uint32_t bytes, uint32_t mbar) {
    asm volatile(
        "cp.async.bulk.shared::cluster.global.mbarrier::complete_tx::bytes "
        "[%0], [%1], %2, [%3];"
        :: "r"(dst), "l"(src), "r"(bytes), "r"(mbar) : "memory");
}
__device__ __forceinline__ uint32_t segaddr(uint32_t base, int r, int kc) {
    return base + r * 128 + ((((kc >> 3) ^ (r & 7)) & 7) << 4);
}

#define SBYTES 98304u   // Ah|Al | B0h|B0l | B1h|B1l

// MODE 0: qkv split  1: roll+residual  2: +bias GELU  3: +bias+addsrc
// Persistent: grid = numSM. 16 consumer warps (32x64 warp tiles -> 4 warps per
// SMSP for latency hiding) + 1 producer warp driving a global-stage TMA ring.
template<int MODE>
__global__ void __launch_bounds__(544) tc_gemm(
    const __nv_bfloat16* __restrict__ Ap, const __nv_bfloat16* __restrict__ Bp,
    float* __restrict__ O0, float* __restrict__ O1, float* __restrict__ O2,
    const float* __restrict__ bias, const float* __restrict__ addsrc,
    int KT, int Ntot, int NTX, int ntiles)
{
    extern __shared__ char dsm[];
    __shared__ __align__(8) uint64_t s_mbar[4];   // full0 full1 empty0 empty1

    const uint32_t sb  = (cvta_smem(dsm) + 1023u) & ~1023u;
    const uint32_t mbF = cvta_smem(&s_mbar[0]);
    const uint32_t mbE = cvta_smem(&s_mbar[2]);
    const int tid = threadIdx.x;
    const int wid = tid >> 5, lane = tid & 31;

    if (tid == 0) {
        mbar_init(mbF, 1);  mbar_init(mbF + 8, 1);
        mbar_init(mbE, 16); mbar_init(mbE + 8, 16);
        asm volatile("fence.proxy.async.shared::cta;" ::: "memory");
    }
    __syncthreads();

    if (wid == 16) {
        // ---- producer warp: continuous ring across all tiles ----
        if (lane == 0) {
            int gs = 0;
            for (int tile = blockIdx.x; tile < ntiles; tile += gridDim.x) {
                const int ni = tile % NTX, mi = tile / NTX;
                for (int s = 0; s < KT; s++, gs++) {
                    if (gs >= 2) mbar_wait(mbE + (gs & 1) * 8, (uint32_t)(((gs - 2) >> 1) & 1));
                    int b = gs & 1;
                    uint32_t d = sb + b * SBYTES;
                    uint32_t m = mbF + b * 8;
                    mbar_expect_tx(m, SBYTES);
                    bulk_cp(d,         Ap + (((size_t)mi       * KT + s) * 2) * PLANE, 32768, m);
                    bulk_cp(d + 32768, Bp + (((size_t)(2*ni)   * KT + s) * 2) * PLANE, 32768, m);
                    bulk_cp(d + 65536, Bp + (((size_t)(2*ni+1) * KT + s) * 2) * PLANE, 32768, m);
                }
            }
        }
        return;
    }

    // ---- consumer warps (0-15): warp tile 32 (M) x 64 (N) ----
    const int wm = (wid & 3) * 32;          // 4 warps along M
    const int wn = (wid >> 2) * 64;         // 4 warps along N (of 256)
    const int bplane = (wn >> 7);
    const int wnl = wn & 127;
    const int arow0 = wm + (lane & 15);
    const int akc0  = (lane >> 4) * 8;
    const int brow0 = wnl + ((lane >> 4) & 1) * 8 + (lane & 7);
    const int bkc0  = ((lane >> 3) & 1) * 8;
    const int rb0 = wm + (lane >> 2);
    const int cb  = wn + (lane & 3) * 2;

    int gs = 0;
    for (int tile = blockIdx.x; tile < ntiles; tile += gridDim.x) {
        const int ni = tile % NTX, mi = tile / NTX;

        float acc[2][8][4];
        #pragma unroll
        for (int a = 0; a < 2; a++)
            #pragma unroll
            for (int b = 0; b < 8; b++)
                #pragma unroll
                for (int c = 0; c < 4; c++) acc[a][b][c] = 0.0f;

        for (int s = 0; s < KT; s++, gs++) {
            int b = gs & 1;
            mbar_wait(mbF + b * 8, (uint32_t)((gs >> 1) & 1));
            const uint32_t Ah = sb + b * SBYTES;
            const uint32_t Al = Ah + 16384;
            const uint32_t Bh = Ah + 32768 + bplane * 32768;
            const uint32_t Bl = Bh + 16384;

            #pragma unroll
            for (int kf = 0; kf < 4; kf++) {
                const int k0 = kf * 16;
                const int akc = k0 + akc0;
                const int bkc = k0 + bkc0;
                uint32_t fa[2][4], fal[2][4], fbh[4][4], fbl[4][4];

                // ---- issue all fragment loads up front, in pass order ----
                #pragma unroll
                for (int mt = 0; mt < 2; mt++)
                    ldsm4(fa[mt], segaddr(Ah, arow0 + mt * 16, akc));
                #pragma unroll
                for (int j = 0; j < 4; j++)
                    ldsm4(fbh[j], segaddr(Bh, brow0 + j * 16, bkc));
                #pragma unroll
                for (int mt = 0; mt < 2; mt++)
                    ldsm4(fal[mt], segaddr(Al, arow0 + mt * 16, akc));
                #pragma unroll
                for (int j = 0; j < 4; j++)
                    ldsm4(fbl[j], segaddr(Bl, brow0 + j * 16, bkc));
                // stage fully read once these loads retire; release early
                if (kf == 3 && lane == 0) mbar_arrive(mbE + b * 8);

                // ---- pass 1: Ah * Bh ----
                #pragma unroll
                for (int mt = 0; mt < 2; mt++)
                    #pragma unroll
                    for (int j = 0; j < 4; j++) {
                        mma16816(acc[mt][2*j],   fa[mt], &fbh[j][0]);
                        mma16816(acc[mt][2*j+1], fa[mt], &fbh[j][2]);
                    }
                // ---- pass 2: Al * Bh ----
                #pragma unroll
                for (int mt = 0; mt < 2; mt++)
                    #pragma unroll
                    for (int j = 0; j < 4; j++) {
                        mma16816(acc[mt][2*j],   fal[mt], &fbh[j][0]);
                        mma16816(acc[mt][2*j+1], fal[mt], &fbh[j][2]);
                    }
                // ---- pass 3: Ah * Bl ----
                #pragma unroll
                for (int mt = 0; mt < 2; mt++)
                    #pragma unroll
                    for (int j = 0; j < 4; j++) {
                        mma16816(acc[mt][2*j],   fa[mt], &fbl[j][0]);
                        mma16816(acc[mt][2*j+1], fa[mt], &fbl[j][2]);
                    }
            }
        }

        // epilogue for this tile (producer already prefetching next tile)
        const int rb = mi * 128 + rb0;
        #pragma unroll
        for (int mt = 0; mt < 2; mt++) {
            #pragma unroll
            for (int half = 0; half < 2; half++) {
                const int m = rb + mt * 16 + half * 8;
                #pragma unroll
                for (int nt = 0; nt < 8; nt++) {
                    const int n = ni * 256 + cb + nt * 8;
                    float v0 = acc[mt][nt][half * 2 + 0];
                    float v1 = acc[mt][nt][half * 2 + 1];
                    if (MODE == 0) {
                        int buf = n >> 9, col = n & 511;
                        float* dst = (buf == 0 ? O0 : (buf == 1 ? O1 : O2));
                        *(float2*)(dst + (size_t)m * CC + col) = make_float2(v0, v1);
                    } else if (MODE == 1) {
                        int bt = m >> 12, l = m & (LL - 1);
                        size_t mrow = ((size_t)(bt << 12) | ((l + SHIFT) & (LL - 1)));
                        float2 r0 = *(const float2*)(addsrc + mrow * Ntot + n);
                        *(float2*)(O0 + mrow * Ntot + n) = make_float2(v0 + r0.x, v1 + r0.y);
                    } else if (MODE == 2) {
                        float2 b2 = *(const float2*)(bias + n);
                        *(float2*)(O0 + (size_t)m * Ntot + n) =
                            make_float2(gelu_f(v0 + b2.x), gelu_f(v1 + b2.y));
                    } else {
                        float2 b2 = *(const float2*)(bias + n);
                        float2 r0 = *(const float2*)(addsrc + (size_t)m * Ntot + n);
                        *(float2*)(O0 + (size_t)m * Ntot + n) =
                            make_float2(v0 + b2.x + r0.x, v1 + b2.y + r0.y);
                    }
                }
            }
        }
    }
}

// ---------------- window attention: 4x4 microtile version ---------------------
#define ATT_SQ   0
#define ATT_SK   (64*68)
#define ATT_SV   (ATT_SK + 64*64)
#define ATT_SB   (ATT_SV + 64*64)
#define ATT_SMEM ((ATT_SB + 128) * 4)

__global__ void __launch_bounds__(256) attn_kernel(
    const float* __restrict__ q, const float* __restrict__ k, const float* __restrict__ v,
    const float* __restrict__ rel_table,
    float* __restrict__ attn_out, __nv_bfloat16* __restrict__ ctxp, int write_attn)
{
    extern __shared__ float smf[];
    float* sQ = smf + ATT_SQ;
    float* sK = smf + ATT_SK;
    float* sV = smf + ATT_SV;
    float* sB = smf + ATT_SB;

    const int h = blockIdx.x;
    const int w = blockIdx.y;
    const int tid = threadIdx.x;
    const size_t base = (size_t)w * WSZ * CC + (size_t)h * DK;

    {
        int t = tid >> 2, qd = tid & 3;
        #pragma unroll
        for (int i = 0; i < 4; i++) {
            int d0 = qd * 16 + i * 4;
            float4 qv = *(const float4*)(q + base + (size_t)t * CC + d0);
            sQ[(d0+0)*68 + t] = qv.x; sQ[(d0+1)*68 + t] = qv.y;
            sQ[(d0+2)*68 + t] = qv.z; sQ[(d0+3)*68 + t] = qv.w;
            float4 kv = *(const float4*)(k + base + (size_t)t * CC + d0);
            sK[(d0+0)*64 + t] = kv.x; sK[(d0+1)*64 + t] = kv.y;
            sK[(d0+2)*64 + t] = kv.z; sK[(d0+3)*64 + t] = kv.w;
            float4 vv = *(const float4*)(v + base + (size_t)t * CC + d0);
            *(float4*)(sV + t * 64 + d0) = vv;
        }
        if (tid < 127) sB[tid] = rel_table[tid * NH + h];
    }
    __syncthreads();

    const int ty = tid >> 4, tx = tid & 15;
    float sc[4][4];
    #pragma unroll
    for (int i = 0; i < 4; i++)
        #pragma unroll
        for (int j = 0; j < 4; j++) sc[i][j] = 0.0f;

    #pragma unroll 8
    for (int d = 0; d < 64; d++) {
        float4 qv = *(const float4*)(sQ + d * 68 + ty * 4);
        float4 kv = *(const float4*)(sK + d * 64 + tx * 4);
        float qa[4] = {qv.x, qv.y, qv.z, qv.w};
        float ka[4] = {kv.x, kv.y, kv.z, kv.w};
        #pragma unroll
        for (int i = 0; i < 4; i++)
            #pragma unroll
            for (int j = 0; j < 4; j++)
                sc[i][j] += qa[i] * ka[j];
    }

    const bool last = ((w & (NW - 1)) == (NW - 1));
    #pragma unroll
    for (int i = 0; i < 4; i++) {
        int t = ty * 4 + i;
        #pragma unroll
        for (int j = 0; j < 4; j++) {
            int t2 = tx * 4 + j;
            float s = sc[i][j] * 0.125f + sB[t - t2 + 63];
            if (last && ((t < 32) != (t2 < 32))) s -= 100.0f;
            sc[i][j] = s;
        }
    }

    #pragma unroll
    for (int i = 0; i < 4; i++) {
        float m = fmaxf(fmaxf(sc[i][0], sc[i][1]), fmaxf(sc[i][2], sc[i][3]));
        m = fmaxf(m, __shfl_xor_sync(0xffffffffu, m, 1));
        m = fmaxf(m, __shfl_xor_sync(0xffffffffu, m, 2));
        m = fmaxf(m, __shfl_xor_sync(0xffffffffu, m, 4));
        m = fmaxf(m, __shfl_xor_sync(0xffffffffu, m, 8));
        float s = 0.0f;
        #pragma unroll
        for (int j = 0; j < 4; j++) { sc[i][j] = __expf(sc[i][j] - m); s += sc[i][j]; }
        s += __shfl_xor_sync(0xffffffffu, s, 1);
        s += __shfl_xor_sync(0xffffffffu, s, 2);
        s += __shfl_xor_sync(0xffffffffu, s, 4);
        s += __shfl_xor_sync(0xffffffffu, s, 8);
        float inv = 1.0f / s;
        #pragma unroll
        for (int j = 0; j < 4; j++) sc[i][j] *= inv;
    }

    if (write_attn) {
        #pragma unroll
        for (int i = 0; i < 4; i++) {
            int t = ty * 4 + i;
            size_t ao = ((((size_t)w * NH + h) * WSZ) + t) * WSZ + tx * 4;
            *(float4*)(attn_out + ao) = make_float4(sc[i][0], sc[i][1], sc[i][2], sc[i][3]);
        }
    }

    __syncthreads();
    #pragma unroll
    for (int i = 0; i < 4; i++) {
        int t = ty * 4 + i;
        #pragma unroll
        for (int j = 0; j < 4; j++)
            sQ[(tx * 4 + j) * 68 + t] = sc[i][j];
    }
    __syncthreads();

    float oa[4][4];
    #pragma unroll
    for (int i = 0; i < 4; i++)
        #pragma unroll
        for (int j = 0; j < 4; j++) oa[i][j] = 0.0f;

    #pragma unroll 8
    for (int t2 = 0; t2 < 64; t2++) {
        float4 sv = *(const float4*)(sQ + t2 * 68 + ty * 4);
        float4 vv = *(const float4*)(sV + t2 * 64 + tx * 4);
        float sa[4] = {sv.x, sv.y, sv.z, sv.w};
        float va[4] = {vv.x, vv.y, vv.z, vv.w};
        #pragma unroll
        for (int i = 0; i < 4; i++)
            #pragma unroll
            for (int j = 0; j < 4; j++)
                oa[i][j] += sa[i] * va[j];
    }

    #pragma unroll
    for (int i = 0; i < 4; i++) {
        int gr = w * WSZ + ty * 4 + i;
        int mi = gr >> 7, r = gr & 127;
        store_hl8(planeptr(ctxp, mi, 0, h, 8), planeptr(ctxp, mi, 1, h, 8),
                  r, tx * 4, make_float4(oa[i][0], oa[i][1], oa[i][2], oa[i][3]));
    }
}

// ---------------- dwconv (k=3) + GELU -> packed planes (KT=32) ----------------
__global__ void __launch_bounds__(256) dwconv_kernel(
    const float* __restrict__ f, const float* __restrict__ c2w,
    const float* __restrict__ c2b, __nv_bfloat16* __restrict__ outp)
{
    size_t idx = (size_t)blockIdx.x * blockDim.x + threadIdx.x;
    if (idx >= (size_t)TOK * HID / 4) return;
    size_t e = idx * 4;
    int ch = (int)(e % HID);
    size_t row = e / HID;
    int l = (int)(row & (LL - 1));

    float4 fc = *(const float4*)(f + e);
    float4 fm = make_float4(0.f, 0.f, 0.f, 0.f);
    float4 fp = make_float4(0.f, 0.f, 0.f, 0.f);
    if (l > 0)      fm = *(const float4*)(f + e - HID);
    if (l < LL - 1) fp = *(const float4*)(f + e + HID);

    float rr[4];
    float fmv[4] = {fm.x, fm.y, fm.z, fm.w};
    float fcv[4] = {fc.x, fc.y, fc.z, fc.w};
    float fpv[4] = {fp.x, fp.y, fp.z, fp.w};
    #pragma unroll
    for (int j = 0; j < 4; j++) {
        int c = ch + j;
        float dw = fmv[j] * c2w[c*3+0] + fcv[j] * c2w[c*3+1] + fpv[j] * c2w[c*3+2] + c2b[c];
        rr[j] = gelu_f(dw + fcv[j]);
    }
    int mi = (int)(row >> 7), r = (int)(row & 127);
    int ki = ch >> 6, cc = ch & 63;
    store_hl8(planeptr(outp, mi, 0, ki, 32), planeptr(outp, mi, 1, ki, 32),
              r, cc, make_float4(rr[0], rr[1], rr[2], rr[3]));
}

// ---------------- launch ------------------------------------------------------
extern "C" void kernel_launch(void* const* d_in, const int* in_sizes, int n_in,
                              void* d_out, int out_size)
{
    const float* x      = (const float*)d_in[0];
    const float* ln1_g  = (const float*)d_in[1];
    const float* ln1_b  = (const float*)d_in[2];
    const float* w_q    = (const float*)d_in[3];
    const float* w_k    = (const float*)d_in[4];
    const float* w_v    = (const float*)d_in[5];
    const float* w_o    = (const float*)d_in[6];
    const float* rel    = (const float*)d_in[7];
    const float* ln2_g  = (const float*)d_in[8];
    const float* ln2_b  = (const float*)d_in[9];
    const float* c1_w   = (const float*)d_in[10];
    const float* c1_b   = (const float*)d_in[11];
    const float* c2_w   = (const float*)d_in[12];
    const float* c2_b   = (const float*)d_in[13];
    const float* c3_w   = (const float*)d_in[14];
    const float* c3_b   = (const float*)d_in[15];
    float* out = (float*)d_out;

    __nv_bfloat16 *hp, *ctxp, *f2p, *wqkvp, *wop, *c1wp, *c3wp;
    float *q, *k, *v, *f;
    cudaGetSymbolAddress((void**)&hp,    g_hp);
    cudaGetSymbolAddress((void**)&ctxp,  g_ctxp);
    cudaGetSymbolAddress((void**)&f2p,   g_f2p);
    cudaGetSymbolAddress((void**)&wqkvp, g_wqkvp);
    cudaGetSymbolAddress((void**)&wop,   g_wop);
    cudaGetSymbolAddress((void**)&c1wp,  g_c1wp);
    cudaGetSymbolAddress((void**)&c3wp,  g_c3wp);
    cudaGetSymbolAddress((void**)&q, g_q);
    cudaGetSymbolAddress((void**)&k, g_k);
    cudaGetSymbolAddress((void**)&v, g_v);
    cudaGetSymbolAddress((void**)&f, g_f);
    float* y1 = q;

    const int write_attn = ((size_t)out_size >= Y_ELEMS + ATTN_ELEMS) ? 1 : 0;
    float* attn_out = out + Y_ELEMS;

    int nsm = 148;
    cudaDeviceGetAttribute(&nsm, cudaDevAttrMultiProcessorCount, 0);

    const int dyn = 2 * SBYTES + 1024;
    cudaFuncSetAttribute(tc_gemm<0>, cudaFuncAttributeMaxDynamicSharedMemorySize, dyn);
    cudaFuncSetAttribute(tc_gemm<1>, cudaFuncAttributeMaxDynamicSharedMemorySize, dyn);
    cudaFuncSetAttribute(tc_gemm<2>, cudaFuncAttributeMaxDynamicSharedMemorySize, dyn);
    cudaFuncSetAttribute(tc_gemm<3>, cudaFuncAttributeMaxDynamicSharedMemorySize, dyn);
    cudaFuncSetAttribute(attn_kernel, cudaFuncAttributeMaxDynamicSharedMemorySize, ATT_SMEM);

    // Keep tc_gemm<0> at MY launch idx 3 (== ncu -s 5 capture with the 2
    // harness-prepended launches).
    prep_qkv<<<dim3(12, 8), 256>>>(w_q, w_k, w_v, wqkvp);     // my 0
    ln_kernel<<<TOK, 128>>>(x, hp, ln1_g, ln1_b, 1);          // my 1
    prep_weights<<<dim3(4, 8), 256>>>(w_o, wop, CC, 0);       // my 2

    tc_gemm<0><<<nsm, 544, dyn>>>(hp, wqkvp, q, k, v,
                                  nullptr, nullptr, 8, 1536, 6, 6 * (TOK/128)); // my 3

    attn_kernel<<<dim3(NH, BB*NW), 256, ATT_SMEM>>>(q, k, v, rel, attn_out, ctxp, write_attn);

    tc_gemm<1><<<nsm, 544, dyn>>>(ctxp, wop, y1, nullptr, nullptr,
                                  nullptr, x, 8, CC, 2, 2 * (TOK/128));

    ln_kernel<<<TOK, 128>>>(y1, hp, ln2_g, ln2_b, 0);

    prep_weights<<<dim3(16, 8), 256>>>(c1_w, c1wp, CC, 0);
    tc_gemm<2><<<nsm, 544, dyn>>>(hp, c1wp, f, nullptr, nullptr,
                                  c1_b, nullptr, 8, HID, 8, 8 * (TOK/128));

    size_t nthread = (size_t)TOK * HID / 4;
    dwconv_kernel<<<(unsigned)((nthread + 255) / 256), 256>>>(f, c2_w, c2_b, f2p);

    prep_weights<<<dim3(4, 32), 256>>>(c3_w, c3wp, HID, 0);
    tc_gemm<3><<<nsm, 544, dyn>>>(f2p, c3wp, out, nullptr, nullptr,
                                  c3_b, y1, 32, CC, 2, 2 * (TOK/128));
}